// round 7
// baseline (speedup 1.0000x reference)
#include <cuda_runtime.h>
#include <cuda_bf16.h>
#include <cstdint>
#include <cmath>

// Problem constants: B=4, S=4096, E=1024, H=16, hd=64
#define TOK     16384            // B*S
#define EDIM    1024
#define NHEAD   16
#define HDIM    64
#define BH      64               // B*H
#define SEQ     4096
#define EPSN    1e-4f

// ---------------- scratch (static device memory; no allocations) -----------
__device__ float g_wn[4u * 1024u * 1024u];          // 4 normalized weights (tf32-rounded)
__device__ float g_qt[(size_t)TOK * EDIM];          // query, tf32-rounded
__device__ float g_q[(size_t)TOK * EDIM];
__device__ float g_k[(size_t)TOK * EDIM];
__device__ float g_v[(size_t)TOK * EDIM];
__device__ float g_o[(size_t)TOK * EDIM];           // attn output, tf32-rounded
__device__ float g_scp[4u * BH * HDIM * HDIM];      // partial scores (s-split)
__device__ float g_attn[BH * HDIM * HDIM];          // softmaxed attn

// ======================= PTX helpers ========================================
__device__ __forceinline__ uint32_t smem_to_u32(const void* p) {
    uint32_t a;
    asm("{ .reg .u64 t; cvta.to.shared.u64 t, %1; cvt.u32.u64 %0, t; }" : "=r"(a) : "l"(p));
    return a;
}
__device__ __forceinline__ float to_tf32(float x) {
    float r;
    asm("cvt.rna.tf32.f32 %0, %1;" : "=f"(r) : "f"(x));
    return r;
}

#define CP_ASYNC16(dst, src) \
    asm volatile("cp.async.cg.shared.global [%0], [%1], 16;" :: "r"(dst), "l"(src))
#define CP_COMMIT()  asm volatile("cp.async.commit_group;" ::: "memory")
#define CP_WAIT2()   asm volatile("cp.async.wait_group 2;" ::: "memory")

// m16n8k8 tf32 MMA (arch-portable; lowers to fallback HMMA on sm_103)
__device__ __forceinline__ void mma_tf32(float* d, const uint32_t* a, const uint32_t* b) {
    asm volatile(
        "mma.sync.aligned.m16n8k8.row.col.f32.tf32.tf32.f32 "
        "{%0,%1,%2,%3}, {%4,%5,%6,%7}, {%8,%9}, {%0,%1,%2,%3};"
        : "+f"(d[0]), "+f"(d[1]), "+f"(d[2]), "+f"(d[3])
        : "r"(a[0]), "r"(a[1]), "r"(a[2]), "r"(a[3]), "r"(b[0]), "r"(b[1]));
}

// ldmatrix x4: four 8x8-b16 matrices == four 8x4-tf32 fragments
__device__ __forceinline__ void ldsm_x4(uint32_t& r0, uint32_t& r1, uint32_t& r2,
                                        uint32_t& r3, uint32_t addr) {
    asm volatile("ldmatrix.sync.aligned.m8n8.x4.shared.b16 {%0,%1,%2,%3}, [%4];"
                 : "=r"(r0), "=r"(r1), "=r"(r2), "=r"(r3) : "r"(addr));
}

// ======================= tf32 mma.sync GEMM =================================
// C[16384,1024] = A[16384,1024(K)] * B[1024,1024(K)]^T   (row-major, K contiguous)
// CTA tile 128(M) x 256(N), K-chunk 32, 3-stage cp.async pipeline.
// 8 warps = 2(M) x 4(N); warp tile 64x64 via 4(M) x 8(N) m16n8k8 fragments.
// Fragments loaded with ldmatrix.x4 (tf32-as-b16 trick).
#define PADW    36                        // floats per smem row (32 + 4 pad)
#define AROWS   128
#define BROWS   256
#define STAGEF  ((AROWS + BROWS) * PADW)  // floats per stage
#define GEMM_SMEM_BYTES (3 * STAGEF * 4)  // 165888 bytes

__global__ __launch_bounds__(256, 1)
void gemm_tc_kernel(const float* __restrict__ A, const float* __restrict__ B,
                    float* __restrict__ C, const float* __restrict__ Res, float alpha)
{
    extern __shared__ __align__(16) float smem[];
    const uint32_t sbase = smem_to_u32(smem);

    const int tid = threadIdx.x;
    const int wid = tid >> 5;
    const int lane = tid & 31;
    const int g = lane >> 2;            // group id 0..7
    const int tig = lane & 3;           // thread-in-group 0..3
    const int m0 = (wid >> 2) * 64;     // warp M offset in CTA tile
    const int n0 = (wid & 3) * 64;      // warp N offset in CTA tile
    const int bm = blockIdx.y * 128;
    const int bn = blockIdx.x * 256;

    // ldmatrix per-lane address offsets (in floats), q = lane>>3, r = lane&7
    const int q = lane >> 3, r = lane & 7;
    const int laneA = ((q & 1) * 8 + r) * PADW + (q >> 1) * 4;   // A: rows pair-major, k second
    const int laneB = ((q >> 1) * 8 + r) * PADW + (q & 1) * 4;   // B: k pair-major within row pair

    const char* gA = (const char*)(A + (size_t)bm * EDIM);
    const char* gB = (const char*)(B + (size_t)bn * EDIM);

    // loader: one K-chunk (A: 128 rows, B: 256 rows; 32 floats each) into stage st
    auto load_chunk = [&](int kc, int st) {
        uint32_t dA = sbase + (uint32_t)st * (STAGEF * 4);
        uint32_t dB = dA + AROWS * PADW * 4;
        int koff = kc * 128;                 // byte offset of chunk within a row
        #pragma unroll
        for (int rr = 0; rr < 4; rr++) {     // A: 1024 float4 slots
            int f = tid + rr * 256;
            int row = f >> 3;
            int seg = (f & 7) * 16;
            CP_ASYNC16(dA + (uint32_t)(row * (PADW * 4) + seg),
                       gA + (size_t)row * (EDIM * 4) + koff + seg);
        }
        #pragma unroll
        for (int rr = 0; rr < 8; rr++) {     // B: 2048 float4 slots
            int f = tid + rr * 256;
            int row = f >> 3;
            int seg = (f & 7) * 16;
            CP_ASYNC16(dB + (uint32_t)(row * (PADW * 4) + seg),
                       gB + (size_t)row * (EDIM * 4) + koff + seg);
        }
    };

    float acc[4][8][4];
    #pragma unroll
    for (int i = 0; i < 4; i++)
        #pragma unroll
        for (int j = 0; j < 8; j++)
            #pragma unroll
            for (int c = 0; c < 4; c++) acc[i][j][c] = 0.f;

    load_chunk(0, 0); CP_COMMIT();
    load_chunk(1, 1); CP_COMMIT();

    for (int c = 0; c < 32; c++) {
        if (c + 2 < 32) load_chunk(c + 2, (c + 2) % 3);
        CP_COMMIT();                      // always commit (possibly empty group)
        CP_WAIT2();                       // chunk c complete
        __syncthreads();

        const uint32_t stA = sbase + (uint32_t)(c % 3) * (STAGEF * 4);
        const uint32_t stB = stA + AROWS * PADW * 4;
        const uint32_t aBase = stA + (uint32_t)((m0 * PADW + laneA) * 4);
        const uint32_t bBase = stB + (uint32_t)((n0 * PADW + laneB) * 4);

        #pragma unroll
        for (int ks = 0; ks < 4; ks++) {
            uint32_t a[4][4];
            #pragma unroll
            for (int i = 0; i < 4; i++)
                ldsm_x4(a[i][0], a[i][1], a[i][2], a[i][3],
                        aBase + (uint32_t)(i * (16 * PADW * 4) + ks * 32));
            uint32_t b[8][2];
            #pragma unroll
            for (int jp = 0; jp < 4; jp++)
                ldsm_x4(b[jp * 2][0], b[jp * 2][1], b[jp * 2 + 1][0], b[jp * 2 + 1][1],
                        bBase + (uint32_t)(jp * (16 * PADW * 4) + ks * 32));
            #pragma unroll
            for (int i = 0; i < 4; i++)
                #pragma unroll
                for (int j = 0; j < 8; j++)
                    mma_tf32(acc[i][j], a[i], b[j]);
        }
        __syncthreads();
    }

    // epilogue: c0,c1 -> (row, col..col+1); c2,c3 -> (row+8, ...)
    #pragma unroll
    for (int i = 0; i < 4; i++) {
        int row = bm + m0 + 16 * i + g;
        #pragma unroll
        for (int j = 0; j < 8; j++) {
            int col = bn + n0 + 8 * j + tig * 2;
            float2 v0 = make_float2(acc[i][j][0], acc[i][j][1]);
            float2 v1 = make_float2(acc[i][j][2], acc[i][j][3]);
            if (Res != nullptr) {
                float2 r0 = *(const float2*)(Res + (size_t)row * EDIM + col);
                float2 r1 = *(const float2*)(Res + (size_t)(row + 8) * EDIM + col);
                v0.x = (v0.x + r0.x) * alpha; v0.y = (v0.y + r0.y) * alpha;
                v1.x = (v1.x + r1.x) * alpha; v1.y = (v1.y + r1.y) * alpha;
            }
            *(float2*)(C + (size_t)row * EDIM + col) = v0;
            *(float2*)(C + (size_t)(row + 8) * EDIM + col) = v1;
        }
    }
}

// ---------------- tf32 RNA convert (query) ---------------------------------
__global__ __launch_bounds__(256)
void tf32_convert_kernel(const float* __restrict__ in, float* __restrict__ out)
{
    size_t i = (size_t)(blockIdx.x * 256 + threadIdx.x) * 4;
    float4 v = *(const float4*)(in + i);
    v.x = to_tf32(v.x); v.y = to_tf32(v.y); v.z = to_tf32(v.z); v.w = to_tf32(v.w);
    *(float4*)(out + i) = v;
}

// ---------------- magnitude-preserving weight normalization (-> tf32) ------
__global__ __launch_bounds__(256)
void norm_weights_kernel(const float* __restrict__ wq, const float* __restrict__ wk,
                         const float* __restrict__ wv, const float* __restrict__ wo,
                         const float* __restrict__ gain_p)
{
    int row = blockIdx.x;
    int mat = blockIdx.y;
    const float* W = (mat == 0) ? wq : (mat == 1) ? wk : (mat == 2) ? wv : wo;
    const float* src = W + (size_t)row * EDIM;

    int tid = threadIdx.x;
    float4 w4 = *(const float4*)(src + tid * 4);
    float ss = w4.x * w4.x + w4.y * w4.y + w4.z * w4.z + w4.w * w4.w;

    __shared__ float red[8];
    int lane = tid & 31, warp = tid >> 5;
    #pragma unroll
    for (int o = 16; o > 0; o >>= 1) ss += __shfl_xor_sync(0xffffffffu, ss, o);
    if (lane == 0) red[warp] = ss;
    __syncthreads();
    if (tid == 0) {
        float t = 0.f;
        #pragma unroll
        for (int i = 0; i < 8; i++) t += red[i];
        red[0] = t;
    }
    __syncthreads();
    float scale = (*gain_p * (1.0f / 32.0f)) / (EPSN + sqrtf(red[0]) * (1.0f / 32.0f));

    float* dst = g_wn + (size_t)mat * (1024u * 1024u) + (size_t)row * EDIM + tid * 4;
    *(float4*)dst = make_float4(to_tf32(w4.x * scale), to_tf32(w4.y * scale),
                                to_tf32(w4.z * scale), to_tf32(w4.w * scale));
}

// ---------------- per-head normalization of q and k -------------------------
__global__ __launch_bounds__(512)
void norm_qk_kernel()
{
    int t = blockIdx.x;
    float* buf = (blockIdx.y == 0) ? g_q : g_k;
    int warp = threadIdx.x >> 5;
    int lane = threadIdx.x & 31;
    size_t base = (size_t)t * EDIM + warp * HDIM;
    float a = buf[base + lane];
    float b = buf[base + 32 + lane];
    float ss = a * a + b * b;
    #pragma unroll
    for (int o = 16; o > 0; o >>= 1) ss += __shfl_xor_sync(0xffffffffu, ss, o);
    float inv = 1.0f / (EPSN + sqrtf(ss) * 0.125f);
    buf[base + lane] = a * inv;
    buf[base + 32 + lane] = b * inv;
}

// ---------------- partial scores: scores[bn,h,k] = sum_s qn[s,h]*kn[s,k] ----
__global__ __launch_bounds__(256)
void scores_part_kernel()
{
    int bn = blockIdx.x;
    int chunk = blockIdx.y;
    int b = bn >> 4, n = bn & 15;

    __shared__ float qs[32][64];
    __shared__ float ks[32][64];

    int tid = threadIdx.x;
    int ty = tid >> 4, tx = tid & 15;

    float acc[4][4];
    #pragma unroll
    for (int i = 0; i < 4; i++)
        #pragma unroll
        for (int j = 0; j < 4; j++) acc[i][j] = 0.f;

    size_t tbase = ((size_t)b * SEQ + (size_t)chunk * 1024) * EDIM + n * HDIM;

    for (int s0 = 0; s0 < 1024; s0 += 32) {
        #pragma unroll
        for (int rr = 0; rr < 2; rr++) {
            int f = tid + rr * 256;
            int r2 = f >> 4;
            int cc = (f & 15) * 4;
            size_t gg = tbase + (size_t)(s0 + r2) * EDIM + cc;
            *(float4*)&qs[r2][cc] = *(const float4*)&g_q[gg];
            *(float4*)&ks[r2][cc] = *(const float4*)&g_k[gg];
        }
        __syncthreads();

        #pragma unroll 4
        for (int ss = 0; ss < 32; ss++) {
            float4 q4 = *(const float4*)&qs[ss][ty * 4];
            float4 k4 = *(const float4*)&ks[ss][tx * 4];
            float qa[4] = {q4.x, q4.y, q4.z, q4.w};
            float ka[4] = {k4.x, k4.y, k4.z, k4.w};
            #pragma unroll
            for (int i = 0; i < 4; i++)
                #pragma unroll
                for (int j = 0; j < 4; j++)
                    acc[i][j] = fmaf(qa[i], ka[j], acc[i][j]);
        }
        __syncthreads();
    }

    #pragma unroll
    for (int i = 0; i < 4; i++)
        #pragma unroll
        for (int j = 0; j < 4; j++)
            g_scp[(((size_t)chunk * BH + bn) * HDIM + ty * 4 + i) * HDIM + tx * 4 + j] = acc[i][j];
}

// ---------------- softmax over k (rows of length 64) ------------------------
__global__ __launch_bounds__(256)
void softmax_kernel()
{
    int gw = blockIdx.x * 8 + (threadIdx.x >> 5);
    int lane = threadIdx.x & 31;
    int bn = gw >> 6, h = gw & 63;

    float v0 = 0.f, v1 = 0.f;
    #pragma unroll
    for (int c = 0; c < 4; c++) {
        size_t o = (((size_t)c * BH + bn) * HDIM + h) * HDIM;
        v0 += g_scp[o + lane];
        v1 += g_scp[o + 32 + lane];
    }
    v0 *= (1.0f / 64.0f);
    v1 *= (1.0f / 64.0f);

    float m = fmaxf(v0, v1);
    #pragma unroll
    for (int o = 16; o > 0; o >>= 1) m = fmaxf(m, __shfl_xor_sync(0xffffffffu, m, o));
    float e0 = __expf(v0 - m), e1 = __expf(v1 - m);
    float s = e0 + e1;
    #pragma unroll
    for (int o = 16; o > 0; o >>= 1) s += __shfl_xor_sync(0xffffffffu, s, o);
    float inv = 1.0f / s;

    size_t idx = ((size_t)bn * HDIM + h) * HDIM;
    g_attn[idx + lane] = e0 * inv;
    g_attn[idx + 32 + lane] = e1 * inv;
}

// ---------------- apply attention: o[s,h] = sum_k attn[h,k] * v[s,k] --------
__global__ __launch_bounds__(256)
void o_apply_kernel()
{
    int bn = blockIdx.x;
    int st = blockIdx.y;
    int b = bn >> 4, n = bn & 15;

    __shared__ float at[64 * 65];
    __shared__ float vt[64 * 65];

    int tid = threadIdx.x;
    size_t abase = (size_t)bn * HDIM * HDIM;
    #pragma unroll
    for (int rr = 0; rr < 16; rr++) {
        int e = tid + rr * 256;
        int h = e >> 6, k = e & 63;
        at[k * 65 + h] = g_attn[abase + e];
    }
    size_t vbase = ((size_t)b * SEQ + (size_t)st * 64) * EDIM + n * HDIM;
    #pragma unroll
    for (int rr = 0; rr < 16; rr++) {
        int e = tid + rr * 256;
        int s = e >> 6, k = e & 63;
        vt[k * 65 + s] = g_v[vbase + (size_t)s * EDIM + k];
    }
    __syncthreads();

    int ty = tid >> 4, tx = tid & 15;
    int s0 = ty * 4, h0 = tx * 4;
    float acc[4][4];
    #pragma unroll
    for (int i = 0; i < 4; i++)
        #pragma unroll
        for (int j = 0; j < 4; j++) acc[i][j] = 0.f;

    #pragma unroll 4
    for (int k = 0; k < 64; k++) {
        float av[4], vv[4];
        #pragma unroll
        for (int j = 0; j < 4; j++) av[j] = at[k * 65 + h0 + j];
        #pragma unroll
        for (int i = 0; i < 4; i++) vv[i] = vt[k * 65 + s0 + i];
        #pragma unroll
        for (int i = 0; i < 4; i++)
            #pragma unroll
            for (int j = 0; j < 4; j++)
                acc[i][j] = fmaf(av[j], vv[i], acc[i][j]);
    }

    size_t obase = ((size_t)b * SEQ + (size_t)st * 64) * EDIM + n * HDIM;
    #pragma unroll
    for (int i = 0; i < 4; i++)
        #pragma unroll
        for (int j = 0; j < 4; j++)
            g_o[obase + (size_t)(s0 + i) * EDIM + h0 + j] = to_tf32(acc[i][j]);
}

// ---------------- host launcher --------------------------------------------
extern "C" void kernel_launch(void* const* d_in, const int* in_sizes, int n_in,
                              void* d_out, int out_size)
{
    const float* query = (const float*)d_in[0];
    const float* gain  = (const float*)d_in[1];
    const float* wq    = (const float*)d_in[2];
    const float* wk    = (const float*)d_in[3];
    const float* wv    = (const float*)d_in[4];
    const float* wo    = (const float*)d_in[5];
    float* out = (float*)d_out;

    float *p_wn, *p_qt, *p_q, *p_k, *p_v, *p_o;
    cudaGetSymbolAddress((void**)&p_wn, g_wn);
    cudaGetSymbolAddress((void**)&p_qt, g_qt);
    cudaGetSymbolAddress((void**)&p_q,  g_q);
    cudaGetSymbolAddress((void**)&p_k,  g_k);
    cudaGetSymbolAddress((void**)&p_v,  g_v);
    cudaGetSymbolAddress((void**)&p_o,  g_o);

    cudaFuncSetAttribute(gemm_tc_kernel,
                         cudaFuncAttributeMaxDynamicSharedMemorySize, GEMM_SMEM_BYTES);

    // 1) normalize weights (tf32-rounded), convert query to tf32
    norm_weights_kernel<<<dim3(1024, 4), 256>>>(wq, wk, wv, wo, gain);
    tf32_convert_kernel<<<TOK * EDIM / 1024, 256>>>(query, p_qt);

    // 2) Q/K/V projections on tensor cores (mma.sync tf32, ldmatrix fragments)
    dim3 ggrid(EDIM / 256, TOK / 128);   // (4, 128)
    gemm_tc_kernel<<<ggrid, 256, GEMM_SMEM_BYTES>>>(p_qt, p_wn + 0u * (1024u * 1024u), p_q, nullptr, 1.0f);
    gemm_tc_kernel<<<ggrid, 256, GEMM_SMEM_BYTES>>>(p_qt, p_wn + 1u * (1024u * 1024u), p_k, nullptr, 1.0f);
    gemm_tc_kernel<<<ggrid, 256, GEMM_SMEM_BYTES>>>(p_qt, p_wn + 2u * (1024u * 1024u), p_v, nullptr, 1.0f);

    // 3) per-head normalize q, k
    norm_qk_kernel<<<dim3(TOK, 2), 512>>>();

    // 4) partial scores over s-chunks
    scores_part_kernel<<<dim3(BH, 4), 256>>>();

    // 5) reduce + softmax
    softmax_kernel<<<512, 256>>>();

    // 6) apply attention weights to v (writes tf32-rounded)
    o_apply_kernel<<<dim3(BH, 64), 256>>>();

    // 7) output projection + residual mix: (res + proj) * sqrt(0.5)
    gemm_tc_kernel<<<ggrid, 256, GEMM_SMEM_BYTES>>>(p_o, p_wn + 3u * (1024u * 1024u), out, query, 0.70710678118654752f);
}

// round 8
// speedup vs baseline: 1.1583x; 1.1583x over previous
#include <cuda_runtime.h>
#include <cuda_bf16.h>
#include <cstdint>
#include <cmath>

// Problem constants: B=4, S=4096, E=1024, H=16, hd=64
#define TOK     16384            // B*S
#define EDIM    1024
#define NHEAD   16
#define HDIM    64
#define BH      64               // B*H
#define SEQ     4096
#define EPSN    1e-4f

// ---------------- scratch (static device memory; no allocations) -----------
__device__ float g_wn[4u * 1024u * 1024u];          // 4 normalized weights (tf32-rounded)
__device__ float g_qt[(size_t)TOK * EDIM];          // query, tf32-rounded
__device__ float g_q[(size_t)TOK * EDIM];
__device__ float g_k[(size_t)TOK * EDIM];
__device__ float g_v[(size_t)TOK * EDIM];
__device__ float g_o[(size_t)TOK * EDIM];           // attn output, tf32-rounded
__device__ float g_scp[4u * BH * HDIM * HDIM];      // partial scores (s-split)
__device__ float g_attn[BH * HDIM * HDIM];          // softmaxed attn

// ======================= PTX helpers ========================================
__device__ __forceinline__ uint32_t smem_to_u32(const void* p) {
    uint32_t a;
    asm("{ .reg .u64 t; cvta.to.shared.u64 t, %1; cvt.u32.u64 %0, t; }" : "=r"(a) : "l"(p));
    return a;
}
__device__ __forceinline__ float to_tf32(float x) {
    float r;
    asm("cvt.rna.tf32.f32 %0, %1;" : "=f"(r) : "f"(x));
    return r;
}

#define CP_ASYNC16(dst, src) \
    asm volatile("cp.async.cg.shared.global [%0], [%1], 16;" :: "r"(dst), "l"(src))
#define CP_COMMIT()  asm volatile("cp.async.commit_group;" ::: "memory")
#define CP_WAIT2()   asm volatile("cp.async.wait_group 2;" ::: "memory")

// m16n8k8 tf32 MMA (arch-portable; lowers to fallback HMMA on sm_103)
__device__ __forceinline__ void mma_tf32(float* d, const uint32_t* a, const uint32_t* b) {
    asm volatile(
        "mma.sync.aligned.m16n8k8.row.col.f32.tf32.tf32.f32 "
        "{%0,%1,%2,%3}, {%4,%5,%6,%7}, {%8,%9}, {%0,%1,%2,%3};"
        : "+f"(d[0]), "+f"(d[1]), "+f"(d[2]), "+f"(d[3])
        : "r"(a[0]), "r"(a[1]), "r"(a[2]), "r"(a[3]), "r"(b[0]), "r"(b[1]));
}

// ldmatrix x4: four 8x8-b16 matrices == four 8x4-tf32 fragments
__device__ __forceinline__ void ldsm_x4(uint32_t& r0, uint32_t& r1, uint32_t& r2,
                                        uint32_t& r3, uint32_t addr) {
    asm volatile("ldmatrix.sync.aligned.m8n8.x4.shared.b16 {%0,%1,%2,%3}, [%4];"
                 : "=r"(r0), "=r"(r1), "=r"(r2), "=r"(r3) : "r"(addr));
}

// ======================= tf32 mma.sync GEMM =================================
// C[16384,1024] = A[16384,1024(K)] * B[1024,1024(K)]^T   (row-major, K contiguous)
// 128x128 CTA tile, K-chunk 32 floats, 3-stage cp.async pipeline, 2 CTAs/SM.
// 8 warps = 2(M) x 4(N); warp tile 64x32 via 4x4 m16n8k8 fragments.
// Fragments fetched with ldmatrix.x4 (tf32-as-b16 trick; validated in R7).
#define PADW   36                       // floats per smem row (32 + 4 pad)
#define STAGEF (128 * PADW)             // 4608 floats per matrix per stage
#define GEMM_SMEM_BYTES (6 * STAGEF * 4)  // A:3 + B:3 stages = 110592

__global__ __launch_bounds__(256, 2)
void gemm_tc_kernel(const float* __restrict__ A, const float* __restrict__ B,
                    float* __restrict__ C, const float* __restrict__ Res, float alpha)
{
    extern __shared__ __align__(16) float smem[];
    float* sA0 = smem;                  // 3 stages of A
    float* sB0 = smem + 3 * STAGEF;     // 3 stages of B
    const uint32_t sbaseA = smem_to_u32(sA0);
    const uint32_t sbaseB = smem_to_u32(sB0);

    const int tid = threadIdx.x;
    const int wid = tid >> 5;
    const int lane = tid & 31;
    const int g = lane >> 2;            // group id 0..7
    const int tig = lane & 3;           // thread-in-group 0..3
    const int m0 = (wid >> 2) * 64;     // warp M offset in tile
    const int n0 = (wid & 3) * 32;      // warp N offset in tile
    const int bm = blockIdx.y * 128;
    const int bn = blockIdx.x * 128;

    // ldmatrix per-lane address offsets (in floats); q = lane>>3, r = lane&7
    const int q = lane >> 3, r = lane & 7;
    const int laneA = ((q & 1) * 8 + r) * PADW + (q >> 1) * 4;   // row-half major, k-half second
    const int laneB = ((q >> 1) * 8 + r) * PADW + (q & 1) * 4;   // k-half major within row pair

    const char* gA = (const char*)(A + (size_t)bm * EDIM);
    const char* gB = (const char*)(B + (size_t)bn * EDIM);

    // loader: one K-chunk (128 rows x 32 floats) of A and B into stage st
    auto load_chunk = [&](int kc, int st) {
        uint32_t dA = sbaseA + (uint32_t)st * (STAGEF * 4);
        uint32_t dB = sbaseB + (uint32_t)st * (STAGEF * 4);
        int koff = kc * 128;                 // byte offset of chunk within row
        #pragma unroll
        for (int rr = 0; rr < 4; rr++) {
            int f = tid + rr * 256;          // 0..1023 float4 slots
            int row = f >> 3;                // 0..127
            int seg = (f & 7) * 16;          // byte seg within chunk row
            uint32_t so = (uint32_t)(row * (PADW * 4) + seg);
            size_t  go = (size_t)row * (EDIM * 4) + koff + seg;
            CP_ASYNC16(dA + so, gA + go);
            CP_ASYNC16(dB + so, gB + go);
        }
    };

    float acc[4][4][4];
    #pragma unroll
    for (int i = 0; i < 4; i++)
        #pragma unroll
        for (int j = 0; j < 4; j++)
            #pragma unroll
            for (int c = 0; c < 4; c++) acc[i][j][c] = 0.f;

    load_chunk(0, 0); CP_COMMIT();
    load_chunk(1, 1); CP_COMMIT();

    for (int c = 0; c < 32; c++) {
        if (c + 2 < 32) load_chunk(c + 2, (c + 2) % 3);
        CP_COMMIT();                      // always commit (possibly empty group)
        CP_WAIT2();                       // chunk c complete
        __syncthreads();

        const uint32_t stA = sbaseA + (uint32_t)(c % 3) * (STAGEF * 4);
        const uint32_t stB = sbaseB + (uint32_t)(c % 3) * (STAGEF * 4);
        const uint32_t aBase = stA + (uint32_t)((m0 * PADW + laneA) * 4);
        const uint32_t bBase = stB + (uint32_t)((n0 * PADW + laneB) * 4);

        #pragma unroll
        for (int ks = 0; ks < 4; ks++) {
            uint32_t a[4][4];
            #pragma unroll
            for (int i = 0; i < 4; i++)
                ldsm_x4(a[i][0], a[i][1], a[i][2], a[i][3],
                        aBase + (uint32_t)(i * (16 * PADW * 4) + ks * 32));
            uint32_t b[4][2];
            #pragma unroll
            for (int jp = 0; jp < 2; jp++)
                ldsm_x4(b[jp * 2][0], b[jp * 2][1], b[jp * 2 + 1][0], b[jp * 2 + 1][1],
                        bBase + (uint32_t)(jp * (16 * PADW * 4) + ks * 32));
            #pragma unroll
            for (int i = 0; i < 4; i++)
                #pragma unroll
                for (int j = 0; j < 4; j++)
                    mma_tf32(acc[i][j], a[i], b[j]);
        }
        __syncthreads();
    }

    // epilogue: c0,c1 -> (row, col..col+1); c2,c3 -> (row+8, ...)
    #pragma unroll
    for (int i = 0; i < 4; i++) {
        int row = bm + m0 + 16 * i + g;
        #pragma unroll
        for (int j = 0; j < 4; j++) {
            int col = bn + n0 + 8 * j + tig * 2;
            float2 v0 = make_float2(acc[i][j][0], acc[i][j][1]);
            float2 v1 = make_float2(acc[i][j][2], acc[i][j][3]);
            if (Res != nullptr) {
                float2 r0 = *(const float2*)(Res + (size_t)row * EDIM + col);
                float2 r1 = *(const float2*)(Res + (size_t)(row + 8) * EDIM + col);
                v0.x = (v0.x + r0.x) * alpha; v0.y = (v0.y + r0.y) * alpha;
                v1.x = (v1.x + r1.x) * alpha; v1.y = (v1.y + r1.y) * alpha;
            }
            *(float2*)(C + (size_t)row * EDIM + col) = v0;
            *(float2*)(C + (size_t)(row + 8) * EDIM + col) = v1;
        }
    }
}

// ---------------- tf32 RNA convert (query) ---------------------------------
__global__ __launch_bounds__(256)
void tf32_convert_kernel(const float* __restrict__ in, float* __restrict__ out)
{
    size_t i = (size_t)(blockIdx.x * 256 + threadIdx.x) * 4;
    float4 v = *(const float4*)(in + i);
    v.x = to_tf32(v.x); v.y = to_tf32(v.y); v.z = to_tf32(v.z); v.w = to_tf32(v.w);
    *(float4*)(out + i) = v;
}

// ---------------- magnitude-preserving weight normalization (-> tf32) ------
__global__ __launch_bounds__(256)
void norm_weights_kernel(const float* __restrict__ wq, const float* __restrict__ wk,
                         const float* __restrict__ wv, const float* __restrict__ wo,
                         const float* __restrict__ gain_p)
{
    int row = blockIdx.x;
    int mat = blockIdx.y;
    const float* W = (mat == 0) ? wq : (mat == 1) ? wk : (mat == 2) ? wv : wo;
    const float* src = W + (size_t)row * EDIM;

    int tid = threadIdx.x;
    float4 w4 = *(const float4*)(src + tid * 4);
    float ss = w4.x * w4.x + w4.y * w4.y + w4.z * w4.z + w4.w * w4.w;

    __shared__ float red[8];
    int lane = tid & 31, warp = tid >> 5;
    #pragma unroll
    for (int o = 16; o > 0; o >>= 1) ss += __shfl_xor_sync(0xffffffffu, ss, o);
    if (lane == 0) red[warp] = ss;
    __syncthreads();
    if (tid == 0) {
        float t = 0.f;
        #pragma unroll
        for (int i = 0; i < 8; i++) t += red[i];
        red[0] = t;
    }
    __syncthreads();
    float scale = (*gain_p * (1.0f / 32.0f)) / (EPSN + sqrtf(red[0]) * (1.0f / 32.0f));

    float* dst = g_wn + (size_t)mat * (1024u * 1024u) + (size_t)row * EDIM + tid * 4;
    *(float4*)dst = make_float4(to_tf32(w4.x * scale), to_tf32(w4.y * scale),
                                to_tf32(w4.z * scale), to_tf32(w4.w * scale));
}

// ---------------- per-head normalization of q and k -------------------------
__global__ __launch_bounds__(512)
void norm_qk_kernel()
{
    int t = blockIdx.x;
    float* buf = (blockIdx.y == 0) ? g_q : g_k;
    int warp = threadIdx.x >> 5;
    int lane = threadIdx.x & 31;
    size_t base = (size_t)t * EDIM + warp * HDIM;
    float a = buf[base + lane];
    float b = buf[base + 32 + lane];
    float ss = a * a + b * b;
    #pragma unroll
    for (int o = 16; o > 0; o >>= 1) ss += __shfl_xor_sync(0xffffffffu, ss, o);
    float inv = 1.0f / (EPSN + sqrtf(ss) * 0.125f);
    buf[base + lane] = a * inv;
    buf[base + 32 + lane] = b * inv;
}

// ---------------- partial scores: scores[bn,h,k] = sum_s qn[s,h]*kn[s,k] ----
__global__ __launch_bounds__(256)
void scores_part_kernel()
{
    int bn = blockIdx.x;
    int chunk = blockIdx.y;
    int b = bn >> 4, n = bn & 15;

    __shared__ float qs[32][64];
    __shared__ float ks[32][64];

    int tid = threadIdx.x;
    int ty = tid >> 4, tx = tid & 15;

    float acc[4][4];
    #pragma unroll
    for (int i = 0; i < 4; i++)
        #pragma unroll
        for (int j = 0; j < 4; j++) acc[i][j] = 0.f;

    size_t tbase = ((size_t)b * SEQ + (size_t)chunk * 1024) * EDIM + n * HDIM;

    for (int s0 = 0; s0 < 1024; s0 += 32) {
        #pragma unroll
        for (int rr = 0; rr < 2; rr++) {
            int f = tid + rr * 256;
            int r2 = f >> 4;
            int cc = (f & 15) * 4;
            size_t gg = tbase + (size_t)(s0 + r2) * EDIM + cc;
            *(float4*)&qs[r2][cc] = *(const float4*)&g_q[gg];
            *(float4*)&ks[r2][cc] = *(const float4*)&g_k[gg];
        }
        __syncthreads();

        #pragma unroll 4
        for (int ss = 0; ss < 32; ss++) {
            float4 q4 = *(const float4*)&qs[ss][ty * 4];
            float4 k4 = *(const float4*)&ks[ss][tx * 4];
            float qa[4] = {q4.x, q4.y, q4.z, q4.w};
            float ka[4] = {k4.x, k4.y, k4.z, k4.w};
            #pragma unroll
            for (int i = 0; i < 4; i++)
                #pragma unroll
                for (int j = 0; j < 4; j++)
                    acc[i][j] = fmaf(qa[i], ka[j], acc[i][j]);
        }
        __syncthreads();
    }

    #pragma unroll
    for (int i = 0; i < 4; i++)
        #pragma unroll
        for (int j = 0; j < 4; j++)
            g_scp[(((size_t)chunk * BH + bn) * HDIM + ty * 4 + i) * HDIM + tx * 4 + j] = acc[i][j];
}

// ---------------- softmax over k (rows of length 64) ------------------------
__global__ __launch_bounds__(256)
void softmax_kernel()
{
    int gw = blockIdx.x * 8 + (threadIdx.x >> 5);
    int lane = threadIdx.x & 31;
    int bn = gw >> 6, h = gw & 63;

    float v0 = 0.f, v1 = 0.f;
    #pragma unroll
    for (int c = 0; c < 4; c++) {
        size_t o = (((size_t)c * BH + bn) * HDIM + h) * HDIM;
        v0 += g_scp[o + lane];
        v1 += g_scp[o + 32 + lane];
    }
    v0 *= (1.0f / 64.0f);
    v1 *= (1.0f / 64.0f);

    float m = fmaxf(v0, v1);
    #pragma unroll
    for (int o = 16; o > 0; o >>= 1) m = fmaxf(m, __shfl_xor_sync(0xffffffffu, m, o));
    float e0 = __expf(v0 - m), e1 = __expf(v1 - m);
    float s = e0 + e1;
    #pragma unroll
    for (int o = 16; o > 0; o >>= 1) s += __shfl_xor_sync(0xffffffffu, s, o);
    float inv = 1.0f / s;

    size_t idx = ((size_t)bn * HDIM + h) * HDIM;
    g_attn[idx + lane] = e0 * inv;
    g_attn[idx + 32 + lane] = e1 * inv;
}

// ---------------- apply attention: o[s,h] = sum_k attn[h,k] * v[s,k] --------
__global__ __launch_bounds__(256)
void o_apply_kernel()
{
    int bn = blockIdx.x;
    int st = blockIdx.y;
    int b = bn >> 4, n = bn & 15;

    __shared__ float at[64 * 65];
    __shared__ float vt[64 * 65];

    int tid = threadIdx.x;
    size_t abase = (size_t)bn * HDIM * HDIM;
    #pragma unroll
    for (int rr = 0; rr < 16; rr++) {
        int e = tid + rr * 256;
        int h = e >> 6, k = e & 63;
        at[k * 65 + h] = g_attn[abase + e];
    }
    size_t vbase = ((size_t)b * SEQ + (size_t)st * 64) * EDIM + n * HDIM;
    #pragma unroll
    for (int rr = 0; rr < 16; rr++) {
        int e = tid + rr * 256;
        int s = e >> 6, k = e & 63;
        vt[k * 65 + s] = g_v[vbase + (size_t)s * EDIM + k];
    }
    __syncthreads();

    int ty = tid >> 4, tx = tid & 15;
    int s0 = ty * 4, h0 = tx * 4;
    float acc[4][4];
    #pragma unroll
    for (int i = 0; i < 4; i++)
        #pragma unroll
        for (int j = 0; j < 4; j++) acc[i][j] = 0.f;

    #pragma unroll 4
    for (int k = 0; k < 64; k++) {
        float av[4], vv[4];
        #pragma unroll
        for (int j = 0; j < 4; j++) av[j] = at[k * 65 + h0 + j];
        #pragma unroll
        for (int i = 0; i < 4; i++) vv[i] = vt[k * 65 + s0 + i];
        #pragma unroll
        for (int i = 0; i < 4; i++)
            #pragma unroll
            for (int j = 0; j < 4; j++)
                acc[i][j] = fmaf(av[j], vv[i], acc[i][j]);
    }

    size_t obase = ((size_t)b * SEQ + (size_t)st * 64) * EDIM + n * HDIM;
    #pragma unroll
    for (int i = 0; i < 4; i++)
        #pragma unroll
        for (int j = 0; j < 4; j++)
            g_o[obase + (size_t)(s0 + i) * EDIM + h0 + j] = to_tf32(acc[i][j]);
}

// ---------------- host launcher --------------------------------------------
extern "C" void kernel_launch(void* const* d_in, const int* in_sizes, int n_in,
                              void* d_out, int out_size)
{
    const float* query = (const float*)d_in[0];
    const float* gain  = (const float*)d_in[1];
    const float* wq    = (const float*)d_in[2];
    const float* wk    = (const float*)d_in[3];
    const float* wv    = (const float*)d_in[4];
    const float* wo    = (const float*)d_in[5];
    float* out = (float*)d_out;

    float *p_wn, *p_qt, *p_q, *p_k, *p_v, *p_o;
    cudaGetSymbolAddress((void**)&p_wn, g_wn);
    cudaGetSymbolAddress((void**)&p_qt, g_qt);
    cudaGetSymbolAddress((void**)&p_q,  g_q);
    cudaGetSymbolAddress((void**)&p_k,  g_k);
    cudaGetSymbolAddress((void**)&p_v,  g_v);
    cudaGetSymbolAddress((void**)&p_o,  g_o);

    cudaFuncSetAttribute(gemm_tc_kernel,
                         cudaFuncAttributeMaxDynamicSharedMemorySize, GEMM_SMEM_BYTES);

    // 1) normalize weights (tf32-rounded), convert query to tf32
    norm_weights_kernel<<<dim3(1024, 4), 256>>>(wq, wk, wv, wo, gain);
    tf32_convert_kernel<<<TOK * EDIM / 1024, 256>>>(query, p_qt);

    // 2) Q/K/V projections on tensor cores (mma.sync tf32 + ldmatrix)
    dim3 ggrid(EDIM / 128, TOK / 128);   // (8, 128)
    gemm_tc_kernel<<<ggrid, 256, GEMM_SMEM_BYTES>>>(p_qt, p_wn + 0u * (1024u * 1024u), p_q, nullptr, 1.0f);
    gemm_tc_kernel<<<ggrid, 256, GEMM_SMEM_BYTES>>>(p_qt, p_wn + 1u * (1024u * 1024u), p_k, nullptr, 1.0f);
    gemm_tc_kernel<<<ggrid, 256, GEMM_SMEM_BYTES>>>(p_qt, p_wn + 2u * (1024u * 1024u), p_v, nullptr, 1.0f);

    // 3) per-head normalize q, k
    norm_qk_kernel<<<dim3(TOK, 2), 512>>>();

    // 4) partial scores over s-chunks
    scores_part_kernel<<<dim3(BH, 4), 256>>>();

    // 5) reduce + softmax
    softmax_kernel<<<512, 256>>>();

    // 6) apply attention weights to v (writes tf32-rounded)
    o_apply_kernel<<<dim3(BH, 64), 256>>>();

    // 7) output projection + residual mix: (res + proj) * sqrt(0.5)
    gemm_tc_kernel<<<ggrid, 256, GEMM_SMEM_BYTES>>>(p_o, p_wn + 3u * (1024u * 1024u), out, query, 0.70710678118654752f);
}

// round 9
// speedup vs baseline: 1.2285x; 1.0606x over previous
#include <cuda_runtime.h>
#include <cuda_bf16.h>
#include <cstdint>
#include <cmath>

// Problem constants: B=4, S=4096, E=1024, H=16, hd=64
#define TOK     16384            // B*S
#define EDIM    1024
#define NHEAD   16
#define HDIM    64
#define BH      64               // B*H
#define SEQ     4096
#define EPSN    1e-4f

// ---------------- scratch (static device memory; no allocations) -----------
__device__ float g_wn[3u * 1024u * 1024u + 1024u * 1024u]; // concat wq|wk|wv|wo (tf32)
__device__ float g_qt[(size_t)TOK * EDIM];                 // query, tf32-rounded
__device__ float g_qkv[3u * (size_t)TOK * EDIM];           // q | k | v outputs
__device__ float g_o[(size_t)TOK * EDIM];                  // attn output (tf32)
__device__ float g_scp[4u * BH * HDIM * HDIM];             // partial scores
__device__ float g_attn[BH * HDIM * HDIM];                 // softmaxed attn

// ======================= PTX helpers ========================================
__device__ __forceinline__ uint32_t smem_to_u32(const void* p) {
    uint32_t a;
    asm("{ .reg .u64 t; cvta.to.shared.u64 t, %1; cvt.u32.u64 %0, t; }" : "=r"(a) : "l"(p));
    return a;
}
__device__ __forceinline__ float to_tf32(float x) {
    float r;
    asm("cvt.rna.tf32.f32 %0, %1;" : "=f"(r) : "f"(x));
    return r;
}

#define CP_ASYNC16(dst, src) \
    asm volatile("cp.async.cg.shared.global [%0], [%1], 16;" :: "r"(dst), "l"(src))
#define CP_COMMIT()  asm volatile("cp.async.commit_group;" ::: "memory")
#define CP_WAIT1()   asm volatile("cp.async.wait_group 1;" ::: "memory")

// m16n8k8 tf32 MMA (arch-portable; lowers to fallback HMMA on sm_103)
__device__ __forceinline__ void mma_tf32(float* d, const uint32_t* a, const uint32_t* b) {
    asm volatile(
        "mma.sync.aligned.m16n8k8.row.col.f32.tf32.tf32.f32 "
        "{%0,%1,%2,%3}, {%4,%5,%6,%7}, {%8,%9}, {%0,%1,%2,%3};"
        : "+f"(d[0]), "+f"(d[1]), "+f"(d[2]), "+f"(d[3])
        : "r"(a[0]), "r"(a[1]), "r"(a[2]), "r"(a[3]), "r"(b[0]), "r"(b[1]));
}

// ldmatrix x4: four 8x8-b16 matrices == four 8x4-tf32 fragments
__device__ __forceinline__ void ldsm_x4(uint32_t& r0, uint32_t& r1, uint32_t& r2,
                                        uint32_t& r3, uint32_t addr) {
    asm volatile("ldmatrix.sync.aligned.m8n8.x4.shared.b16 {%0,%1,%2,%3}, [%4];"
                 : "=r"(r0), "=r"(r1), "=r"(r2), "=r"(r3) : "r"(addr));
}

// ======================= tf32 mma.sync GEMM =================================
// C[row, col_global] = sum_k A[row,k] * B[col_global,k]
// col_global in [0, gridDim.x*128); output matrix index = col_global>>10
// (QKV fused launch: grid.x=24 writes q|k|v thirds of C; others: grid.x=8, mat=0)
// 128x128 CTA tile, K-chunk 32, 3-stage cp.async, ONE barrier per chunk.
#define PADW   36                       // floats per smem row (32 + 4 pad)
#define STAGEF (128 * PADW)             // 4608 floats per matrix per stage
#define GEMM_SMEM_BYTES (6 * STAGEF * 4)  // A:3 + B:3 stages = 110592

__global__ __launch_bounds__(256, 2)
void gemm_tc_kernel(const float* __restrict__ A, const float* __restrict__ B,
                    float* __restrict__ C, const float* __restrict__ Res, float alpha)
{
    extern __shared__ __align__(16) float smem[];
    float* sA0 = smem;                  // 3 stages of A
    float* sB0 = smem + 3 * STAGEF;     // 3 stages of B
    const uint32_t sbaseA = smem_to_u32(sA0);
    const uint32_t sbaseB = smem_to_u32(sB0);

    const int tid = threadIdx.x;
    const int wid = tid >> 5;
    const int lane = tid & 31;
    const int g = lane >> 2;            // group id 0..7
    const int tig = lane & 3;           // thread-in-group 0..3
    const int m0 = (wid >> 2) * 64;     // warp M offset in tile
    const int n0 = (wid & 3) * 32;      // warp N offset in tile
    const int bm = blockIdx.y * 128;
    const int bn = blockIdx.x * 128;    // global col base (may exceed 1024 in QKV mode)

    // output matrix routing (tile never straddles a 1024 boundary)
    const int mat = bn >> 10;
    const int bnl = bn & 1023;          // col base within the output matrix
    float* Cbase = C + (size_t)mat * ((size_t)TOK * EDIM);

    // ldmatrix per-lane address offsets (in floats); q = lane>>3, r = lane&7
    const int q = lane >> 3, r = lane & 7;
    const int laneA = ((q & 1) * 8 + r) * PADW + (q >> 1) * 4;
    const int laneB = ((q >> 1) * 8 + r) * PADW + (q & 1) * 4;

    const char* gA = (const char*)(A + (size_t)bm * EDIM);
    const char* gB = (const char*)(B + (size_t)bn * EDIM);

    // loader: one K-chunk (128 rows x 32 floats) of A and B into stage st
    auto load_chunk = [&](int kc, int st) {
        uint32_t dA = sbaseA + (uint32_t)st * (STAGEF * 4);
        uint32_t dB = sbaseB + (uint32_t)st * (STAGEF * 4);
        int koff = kc * 128;                 // byte offset of chunk within row
        #pragma unroll
        for (int rr = 0; rr < 4; rr++) {
            int f = tid + rr * 256;          // 0..1023 float4 slots
            int row = f >> 3;                // 0..127
            int seg = (f & 7) * 16;          // byte seg within chunk row
            uint32_t so = (uint32_t)(row * (PADW * 4) + seg);
            size_t  go = (size_t)row * (EDIM * 4) + koff + seg;
            CP_ASYNC16(dA + so, gA + go);
            CP_ASYNC16(dB + so, gB + go);
        }
    };

    float acc[4][4][4];
    #pragma unroll
    for (int i = 0; i < 4; i++)
        #pragma unroll
        for (int j = 0; j < 4; j++)
            #pragma unroll
            for (int c = 0; c < 4; c++) acc[i][j][c] = 0.f;

    load_chunk(0, 0); CP_COMMIT();
    load_chunk(1, 1); CP_COMMIT();

    for (int c = 0; c < 32; c++) {
        // pending groups at this point: {c, c+1}; wait until chunk c complete
        CP_WAIT1();
        __syncthreads();   // chunk c visible to all; all warps done reading stage (c-1)%3

        // issue next load into stage (c+2)%3 == (c-1)%3 (reads of it finished above)
        if (c + 2 < 32) load_chunk(c + 2, (c + 2) % 3);
        CP_COMMIT();                      // always commit (possibly empty group)

        const uint32_t stA = sbaseA + (uint32_t)(c % 3) * (STAGEF * 4);
        const uint32_t stB = sbaseB + (uint32_t)(c % 3) * (STAGEF * 4);
        const uint32_t aBase = stA + (uint32_t)((m0 * PADW + laneA) * 4);
        const uint32_t bBase = stB + (uint32_t)((n0 * PADW + laneB) * 4);

        #pragma unroll
        for (int ks = 0; ks < 4; ks++) {
            uint32_t a[4][4];
            #pragma unroll
            for (int i = 0; i < 4; i++)
                ldsm_x4(a[i][0], a[i][1], a[i][2], a[i][3],
                        aBase + (uint32_t)(i * (16 * PADW * 4) + ks * 32));
            uint32_t b[4][2];
            #pragma unroll
            for (int jp = 0; jp < 2; jp++)
                ldsm_x4(b[jp * 2][0], b[jp * 2][1], b[jp * 2 + 1][0], b[jp * 2 + 1][1],
                        bBase + (uint32_t)(jp * (16 * PADW * 4) + ks * 32));
            #pragma unroll
            for (int i = 0; i < 4; i++)
                #pragma unroll
                for (int j = 0; j < 4; j++)
                    mma_tf32(acc[i][j], a[i], b[j]);
        }
    }

    // epilogue: c0,c1 -> (row, col..col+1); c2,c3 -> (row+8, ...)
    #pragma unroll
    for (int i = 0; i < 4; i++) {
        int row = bm + m0 + 16 * i + g;
        #pragma unroll
        for (int j = 0; j < 4; j++) {
            int col = bnl + n0 + 8 * j + tig * 2;
            float2 v0 = make_float2(acc[i][j][0], acc[i][j][1]);
            float2 v1 = make_float2(acc[i][j][2], acc[i][j][3]);
            if (Res != nullptr) {
                float2 r0 = *(const float2*)(Res + (size_t)row * EDIM + col);
                float2 r1 = *(const float2*)(Res + (size_t)(row + 8) * EDIM + col);
                v0.x = (v0.x + r0.x) * alpha; v0.y = (v0.y + r0.y) * alpha;
                v1.x = (v1.x + r1.x) * alpha; v1.y = (v1.y + r1.y) * alpha;
            }
            *(float2*)(Cbase + (size_t)row * EDIM + col) = v0;
            *(float2*)(Cbase + (size_t)(row + 8) * EDIM + col) = v1;
        }
    }
}

// ---------------- tf32 RNA convert (query) ---------------------------------
__global__ __launch_bounds__(256)
void tf32_convert_kernel(const float* __restrict__ in, float* __restrict__ out)
{
    size_t i = (size_t)(blockIdx.x * 256 + threadIdx.x) * 4;
    float4 v = *(const float4*)(in + i);
    v.x = to_tf32(v.x); v.y = to_tf32(v.y); v.z = to_tf32(v.z); v.w = to_tf32(v.w);
    *(float4*)(out + i) = v;
}

// ---------------- magnitude-preserving weight normalization (-> tf32) ------
__global__ __launch_bounds__(256)
void norm_weights_kernel(const float* __restrict__ wq, const float* __restrict__ wk,
                         const float* __restrict__ wv, const float* __restrict__ wo,
                         const float* __restrict__ gain_p)
{
    int row = blockIdx.x;
    int mat = blockIdx.y;
    const float* W = (mat == 0) ? wq : (mat == 1) ? wk : (mat == 2) ? wv : wo;
    const float* src = W + (size_t)row * EDIM;

    int tid = threadIdx.x;
    float4 w4 = *(const float4*)(src + tid * 4);
    float ss = w4.x * w4.x + w4.y * w4.y + w4.z * w4.z + w4.w * w4.w;

    __shared__ float red[8];
    int lane = tid & 31, warp = tid >> 5;
    #pragma unroll
    for (int o = 16; o > 0; o >>= 1) ss += __shfl_xor_sync(0xffffffffu, ss, o);
    if (lane == 0) red[warp] = ss;
    __syncthreads();
    if (tid == 0) {
        float t = 0.f;
        #pragma unroll
        for (int i = 0; i < 8; i++) t += red[i];
        red[0] = t;
    }
    __syncthreads();
    float scale = (*gain_p * (1.0f / 32.0f)) / (EPSN + sqrtf(red[0]) * (1.0f / 32.0f));

    float* dst = g_wn + (size_t)mat * (1024u * 1024u) + (size_t)row * EDIM + tid * 4;
    *(float4*)dst = make_float4(to_tf32(w4.x * scale), to_tf32(w4.y * scale),
                                to_tf32(w4.z * scale), to_tf32(w4.w * scale));
}

// ---------------- partial scores (+ fused q/k head-norm) -------------------
// scores[bn,h,k] = sum_s qn[s,h]*kn[s,k]; q,k normalized per (token,head) in smem
__global__ __launch_bounds__(256)
void scores_part_kernel()
{
    int bn = blockIdx.x;
    int chunk = blockIdx.y;
    int b = bn >> 4, n = bn & 15;

    __shared__ float qs[32][64];
    __shared__ float ks[32][64];

    const float* gq = g_qkv;
    const float* gk = g_qkv + (size_t)TOK * EDIM;

    int tid = threadIdx.x;
    int lane = tid & 31;
    int ty = tid >> 4, tx = tid & 15;

    float acc[4][4];
    #pragma unroll
    for (int i = 0; i < 4; i++)
        #pragma unroll
        for (int j = 0; j < 4; j++) acc[i][j] = 0.f;

    size_t tbase = ((size_t)b * SEQ + (size_t)chunk * 1024) * EDIM + n * HDIM;

    for (int s0 = 0; s0 < 1024; s0 += 32) {
        #pragma unroll
        for (int rr = 0; rr < 2; rr++) {
            int f = tid + rr * 256;
            int r2 = f >> 4;
            int cc = (f & 15) * 4;
            size_t gg = tbase + (size_t)(s0 + r2) * EDIM + cc;
            *(float4*)&qs[r2][cc] = *(const float4*)&gq[gg];
            *(float4*)&ks[r2][cc] = *(const float4*)&gk[gg];
        }
        __syncthreads();

        // fused per-(token,head) normalization: x / (1e-4 + ||x||/8)
        {
            int rowb = (tid >> 5) * 4;        // warp -> 4 rows
            #pragma unroll
            for (int rr = 0; rr < 4; rr++) {
                int row = rowb + rr;
                float qa = qs[row][lane], qb = qs[row][32 + lane];
                float ka = ks[row][lane], kb = ks[row][32 + lane];
                float sq = qa * qa + qb * qb;
                float sk = ka * ka + kb * kb;
                #pragma unroll
                for (int o = 16; o > 0; o >>= 1) {
                    sq += __shfl_xor_sync(0xffffffffu, sq, o);
                    sk += __shfl_xor_sync(0xffffffffu, sk, o);
                }
                float iq = 1.0f / (EPSN + sqrtf(sq) * 0.125f);
                float ik = 1.0f / (EPSN + sqrtf(sk) * 0.125f);
                qs[row][lane] = qa * iq; qs[row][32 + lane] = qb * iq;
                ks[row][lane] = ka * ik; ks[row][32 + lane] = kb * ik;
            }
        }
        __syncthreads();

        #pragma unroll 4
        for (int ss = 0; ss < 32; ss++) {
            float4 q4 = *(const float4*)&qs[ss][ty * 4];
            float4 k4 = *(const float4*)&ks[ss][tx * 4];
            float qa[4] = {q4.x, q4.y, q4.z, q4.w};
            float ka[4] = {k4.x, k4.y, k4.z, k4.w};
            #pragma unroll
            for (int i = 0; i < 4; i++)
                #pragma unroll
                for (int j = 0; j < 4; j++)
                    acc[i][j] = fmaf(qa[i], ka[j], acc[i][j]);
        }
        __syncthreads();
    }

    #pragma unroll
    for (int i = 0; i < 4; i++)
        #pragma unroll
        for (int j = 0; j < 4; j++)
            g_scp[(((size_t)chunk * BH + bn) * HDIM + ty * 4 + i) * HDIM + tx * 4 + j] = acc[i][j];
}

// ---------------- softmax over k (rows of length 64) ------------------------
__global__ __launch_bounds__(256)
void softmax_kernel()
{
    int gw = blockIdx.x * 8 + (threadIdx.x >> 5);
    int lane = threadIdx.x & 31;
    int bn = gw >> 6, h = gw & 63;

    float v0 = 0.f, v1 = 0.f;
    #pragma unroll
    for (int c = 0; c < 4; c++) {
        size_t o = (((size_t)c * BH + bn) * HDIM + h) * HDIM;
        v0 += g_scp[o + lane];
        v1 += g_scp[o + 32 + lane];
    }
    v0 *= (1.0f / 64.0f);
    v1 *= (1.0f / 64.0f);

    float m = fmaxf(v0, v1);
    #pragma unroll
    for (int o = 16; o > 0; o >>= 1) m = fmaxf(m, __shfl_xor_sync(0xffffffffu, m, o));
    float e0 = __expf(v0 - m), e1 = __expf(v1 - m);
    float s = e0 + e1;
    #pragma unroll
    for (int o = 16; o > 0; o >>= 1) s += __shfl_xor_sync(0xffffffffu, s, o);
    float inv = 1.0f / s;

    size_t idx = ((size_t)bn * HDIM + h) * HDIM;
    g_attn[idx + lane] = e0 * inv;
    g_attn[idx + 32 + lane] = e1 * inv;
}

// ---------------- apply attention: o[s,h] = sum_k attn[h,k] * v[s,k] --------
__global__ __launch_bounds__(256)
void o_apply_kernel()
{
    int bn = blockIdx.x;
    int st = blockIdx.y;
    int b = bn >> 4, n = bn & 15;

    __shared__ float at[64 * 65];
    __shared__ float vt[64 * 65];

    const float* gv = g_qkv + 2u * (size_t)TOK * EDIM;

    int tid = threadIdx.x;
    size_t abase = (size_t)bn * HDIM * HDIM;
    #pragma unroll
    for (int rr = 0; rr < 16; rr++) {
        int e = tid + rr * 256;
        int h = e >> 6, k = e & 63;
        at[k * 65 + h] = g_attn[abase + e];
    }
    size_t vbase = ((size_t)b * SEQ + (size_t)st * 64) * EDIM + n * HDIM;
    #pragma unroll
    for (int rr = 0; rr < 16; rr++) {
        int e = tid + rr * 256;
        int s = e >> 6, k = e & 63;
        vt[k * 65 + s] = gv[vbase + (size_t)s * EDIM + k];
    }
    __syncthreads();

    int ty = tid >> 4, tx = tid & 15;
    int s0 = ty * 4, h0 = tx * 4;
    float acc[4][4];
    #pragma unroll
    for (int i = 0; i < 4; i++)
        #pragma unroll
        for (int j = 0; j < 4; j++) acc[i][j] = 0.f;

    #pragma unroll 4
    for (int k = 0; k < 64; k++) {
        float av[4], vv[4];
        #pragma unroll
        for (int j = 0; j < 4; j++) av[j] = at[k * 65 + h0 + j];
        #pragma unroll
        for (int i = 0; i < 4; i++) vv[i] = vt[k * 65 + s0 + i];
        #pragma unroll
        for (int i = 0; i < 4; i++)
            #pragma unroll
            for (int j = 0; j < 4; j++)
                acc[i][j] = fmaf(av[j], vv[i], acc[i][j]);
    }

    size_t obase = ((size_t)b * SEQ + (size_t)st * 64) * EDIM + n * HDIM;
    #pragma unroll
    for (int i = 0; i < 4; i++)
        #pragma unroll
        for (int j = 0; j < 4; j++)
            g_o[obase + (size_t)(s0 + i) * EDIM + h0 + j] = to_tf32(acc[i][j]);
}

// ---------------- host launcher --------------------------------------------
extern "C" void kernel_launch(void* const* d_in, const int* in_sizes, int n_in,
                              void* d_out, int out_size)
{
    const float* query = (const float*)d_in[0];
    const float* gain  = (const float*)d_in[1];
    const float* wq    = (const float*)d_in[2];
    const float* wk    = (const float*)d_in[3];
    const float* wv    = (const float*)d_in[4];
    const float* wo    = (const float*)d_in[5];
    float* out = (float*)d_out;

    float *p_wn, *p_qt, *p_qkv, *p_o;
    cudaGetSymbolAddress((void**)&p_wn,  g_wn);
    cudaGetSymbolAddress((void**)&p_qt,  g_qt);
    cudaGetSymbolAddress((void**)&p_qkv, g_qkv);
    cudaGetSymbolAddress((void**)&p_o,   g_o);

    cudaFuncSetAttribute(gemm_tc_kernel,
                         cudaFuncAttributeMaxDynamicSharedMemorySize, GEMM_SMEM_BYTES);

    // 1) normalize weights (tf32-rounded), convert query to tf32
    norm_weights_kernel<<<dim3(1024, 4), 256>>>(wq, wk, wv, wo, gain);
    tf32_convert_kernel<<<TOK * EDIM / 1024, 256>>>(query, p_qt);

    // 2) fused Q/K/V projection: one launch over concatenated weights
    dim3 qkvgrid(3 * EDIM / 128, TOK / 128);   // (24, 128)
    gemm_tc_kernel<<<qkvgrid, 256, GEMM_SMEM_BYTES>>>(p_qt, p_wn, p_qkv, nullptr, 1.0f);

    // 3) partial scores over s-chunks (q/k head-norm fused in smem)
    scores_part_kernel<<<dim3(BH, 4), 256>>>();

    // 4) reduce + softmax
    softmax_kernel<<<512, 256>>>();

    // 5) apply attention weights to v (writes tf32-rounded)
    o_apply_kernel<<<dim3(BH, 64), 256>>>();

    // 6) output projection + residual mix: (res + proj) * sqrt(0.5)
    dim3 ogrid(EDIM / 128, TOK / 128);         // (8, 128)
    gemm_tc_kernel<<<ogrid, 256, GEMM_SMEM_BYTES>>>(p_o, p_wn + 3u * (1024u * 1024u), out, query, 0.70710678118654752f);
}

// round 10
// speedup vs baseline: 1.3079x; 1.0647x over previous
#include <cuda_runtime.h>
#include <cuda_bf16.h>
#include <cstdint>
#include <cmath>

// Problem constants: B=4, S=4096, E=1024, H=16, hd=64
#define TOK     16384            // B*S
#define EDIM    1024
#define NHEAD   16
#define HDIM    64
#define BH      64               // B*H
#define SEQ     4096
#define EPSN    1e-4f
#define NCHUNK  16               // s-chunks for partial scores

// ---------------- scratch (static device memory; no allocations) -----------
__device__ float g_wn[4u * 1024u * 1024u];                 // concat wq|wk|wv|wo (tf32)
__device__ float g_qkv[3u * (size_t)TOK * EDIM];           // q | k | v outputs
__device__ float g_o[(size_t)TOK * EDIM];                  // attn output (tf32)
__device__ float g_scp[(size_t)NCHUNK * BH * HDIM * HDIM]; // partial scores (16 MB)
__device__ float g_attn[BH * HDIM * HDIM];                 // softmaxed attn

// ======================= PTX helpers ========================================
__device__ __forceinline__ uint32_t smem_to_u32(const void* p) {
    uint32_t a;
    asm("{ .reg .u64 t; cvta.to.shared.u64 t, %1; cvt.u32.u64 %0, t; }" : "=r"(a) : "l"(p));
    return a;
}
__device__ __forceinline__ float to_tf32(float x) {
    float r;
    asm("cvt.rna.tf32.f32 %0, %1;" : "=f"(r) : "f"(x));
    return r;
}

#define CP_ASYNC16(dst, src) \
    asm volatile("cp.async.cg.shared.global [%0], [%1], 16;" :: "r"(dst), "l"(src))
#define CP_COMMIT()  asm volatile("cp.async.commit_group;" ::: "memory")
#define CP_WAIT1()   asm volatile("cp.async.wait_group 1;" ::: "memory")

// m16n8k8 tf32 MMA (arch-portable; lowers to fallback HMMA on sm_103)
__device__ __forceinline__ void mma_tf32(float* d, const uint32_t* a, const uint32_t* b) {
    asm volatile(
        "mma.sync.aligned.m16n8k8.row.col.f32.tf32.tf32.f32 "
        "{%0,%1,%2,%3}, {%4,%5,%6,%7}, {%8,%9}, {%0,%1,%2,%3};"
        : "+f"(d[0]), "+f"(d[1]), "+f"(d[2]), "+f"(d[3])
        : "r"(a[0]), "r"(a[1]), "r"(a[2]), "r"(a[3]), "r"(b[0]), "r"(b[1]));
}

// ldmatrix x4: four 8x8-b16 matrices == four 8x4-tf32 fragments
__device__ __forceinline__ void ldsm_x4(uint32_t& r0, uint32_t& r1, uint32_t& r2,
                                        uint32_t& r3, uint32_t addr) {
    asm volatile("ldmatrix.sync.aligned.m8n8.x4.shared.b16 {%0,%1,%2,%3}, [%4];"
                 : "=r"(r0), "=r"(r1), "=r"(r2), "=r"(r3) : "r"(addr));
}

// ======================= tf32 mma.sync GEMM =================================
// C[row, col_global] = sum_k A[row,k] * B[col_global,k]
// QKV fused: grid.x=24 routes cols to q|k|v thirds; others: grid.x=8, mat=0.
// 128x128 CTA tile, K-chunk 32, 3-stage cp.async, one barrier per chunk.
// A operand may be raw fp32: HW truncates to tf32 (RZ) inside the MMA.
#define PADW   36                       // floats per smem row (32 + 4 pad)
#define STAGEF (128 * PADW)             // 4608 floats per matrix per stage
#define GEMM_SMEM_BYTES (6 * STAGEF * 4)  // A:3 + B:3 stages = 110592

__global__ __launch_bounds__(256, 2)
void gemm_tc_kernel(const float* __restrict__ A, const float* __restrict__ B,
                    float* __restrict__ C, const float* __restrict__ Res, float alpha)
{
    extern __shared__ __align__(16) float smem[];
    float* sA0 = smem;                  // 3 stages of A
    float* sB0 = smem + 3 * STAGEF;     // 3 stages of B
    const uint32_t sbaseA = smem_to_u32(sA0);
    const uint32_t sbaseB = smem_to_u32(sB0);

    const int tid = threadIdx.x;
    const int wid = tid >> 5;
    const int lane = tid & 31;
    const int g = lane >> 2;            // group id 0..7
    const int tig = lane & 3;           // thread-in-group 0..3
    const int m0 = (wid >> 2) * 64;     // warp M offset in tile
    const int n0 = (wid & 3) * 32;      // warp N offset in tile
    const int bm = blockIdx.y * 128;
    const int bn = blockIdx.x * 128;    // global col base (may exceed 1024 in QKV mode)

    // output matrix routing (tile never straddles a 1024 boundary)
    const int mat = bn >> 10;
    const int bnl = bn & 1023;          // col base within the output matrix
    float* Cbase = C + (size_t)mat * ((size_t)TOK * EDIM);

    // ldmatrix per-lane address offsets (in floats); q = lane>>3, r = lane&7
    const int q = lane >> 3, r = lane & 7;
    const int laneA = ((q & 1) * 8 + r) * PADW + (q >> 1) * 4;
    const int laneB = ((q >> 1) * 8 + r) * PADW + (q & 1) * 4;

    const char* gA = (const char*)(A + (size_t)bm * EDIM);
    const char* gB = (const char*)(B + (size_t)bn * EDIM);

    // loader: one K-chunk (128 rows x 32 floats) of A and B into stage st
    auto load_chunk = [&](int kc, int st) {
        uint32_t dA = sbaseA + (uint32_t)st * (STAGEF * 4);
        uint32_t dB = sbaseB + (uint32_t)st * (STAGEF * 4);
        int koff = kc * 128;                 // byte offset of chunk within row
        #pragma unroll
        for (int rr = 0; rr < 4; rr++) {
            int f = tid + rr * 256;          // 0..1023 float4 slots
            int row = f >> 3;                // 0..127
            int seg = (f & 7) * 16;          // byte seg within chunk row
            uint32_t so = (uint32_t)(row * (PADW * 4) + seg);
            size_t  go = (size_t)row * (EDIM * 4) + koff + seg;
            CP_ASYNC16(dA + so, gA + go);
            CP_ASYNC16(dB + so, gB + go);
        }
    };

    float acc[4][4][4];
    #pragma unroll
    for (int i = 0; i < 4; i++)
        #pragma unroll
        for (int j = 0; j < 4; j++)
            #pragma unroll
            for (int c = 0; c < 4; c++) acc[i][j][c] = 0.f;

    load_chunk(0, 0); CP_COMMIT();
    load_chunk(1, 1); CP_COMMIT();

    for (int c = 0; c < 32; c++) {
        // pending groups at this point: {c, c+1}; wait until chunk c complete
        CP_WAIT1();
        __syncthreads();   // chunk c visible; all warps done reading stage (c-1)%3

        if (c + 2 < 32) load_chunk(c + 2, (c + 2) % 3);
        CP_COMMIT();                      // always commit (possibly empty group)

        const uint32_t stA = sbaseA + (uint32_t)(c % 3) * (STAGEF * 4);
        const uint32_t stB = sbaseB + (uint32_t)(c % 3) * (STAGEF * 4);
        const uint32_t aBase = stA + (uint32_t)((m0 * PADW + laneA) * 4);
        const uint32_t bBase = stB + (uint32_t)((n0 * PADW + laneB) * 4);

        #pragma unroll
        for (int ks = 0; ks < 4; ks++) {
            uint32_t a[4][4];
            #pragma unroll
            for (int i = 0; i < 4; i++)
                ldsm_x4(a[i][0], a[i][1], a[i][2], a[i][3],
                        aBase + (uint32_t)(i * (16 * PADW * 4) + ks * 32));
            uint32_t b[4][2];
            #pragma unroll
            for (int jp = 0; jp < 2; jp++)
                ldsm_x4(b[jp * 2][0], b[jp * 2][1], b[jp * 2 + 1][0], b[jp * 2 + 1][1],
                        bBase + (uint32_t)(jp * (16 * PADW * 4) + ks * 32));
            #pragma unroll
            for (int i = 0; i < 4; i++)
                #pragma unroll
                for (int j = 0; j < 4; j++)
                    mma_tf32(acc[i][j], a[i], b[j]);
        }
    }

    // epilogue: c0,c1 -> (row, col..col+1); c2,c3 -> (row+8, ...)
    #pragma unroll
    for (int i = 0; i < 4; i++) {
        int row = bm + m0 + 16 * i + g;
        #pragma unroll
        for (int j = 0; j < 4; j++) {
            int col = bnl + n0 + 8 * j + tig * 2;
            float2 v0 = make_float2(acc[i][j][0], acc[i][j][1]);
            float2 v1 = make_float2(acc[i][j][2], acc[i][j][3]);
            if (Res != nullptr) {
                float2 r0 = *(const float2*)(Res + (size_t)row * EDIM + col);
                float2 r1 = *(const float2*)(Res + (size_t)(row + 8) * EDIM + col);
                v0.x = (v0.x + r0.x) * alpha; v0.y = (v0.y + r0.y) * alpha;
                v1.x = (v1.x + r1.x) * alpha; v1.y = (v1.y + r1.y) * alpha;
            }
            *(float2*)(Cbase + (size_t)row * EDIM + col) = v0;
            *(float2*)(Cbase + (size_t)(row + 8) * EDIM + col) = v1;
        }
    }
}

// ---------------- magnitude-preserving weight normalization (-> tf32) ------
__global__ __launch_bounds__(256)
void norm_weights_kernel(const float* __restrict__ wq, const float* __restrict__ wk,
                         const float* __restrict__ wv, const float* __restrict__ wo,
                         const float* __restrict__ gain_p)
{
    int row = blockIdx.x;
    int mat = blockIdx.y;
    const float* W = (mat == 0) ? wq : (mat == 1) ? wk : (mat == 2) ? wv : wo;
    const float* src = W + (size_t)row * EDIM;

    int tid = threadIdx.x;
    float4 w4 = *(const float4*)(src + tid * 4);
    float ss = w4.x * w4.x + w4.y * w4.y + w4.z * w4.z + w4.w * w4.w;

    __shared__ float red[8];
    int lane = tid & 31, warp = tid >> 5;
    #pragma unroll
    for (int o = 16; o > 0; o >>= 1) ss += __shfl_xor_sync(0xffffffffu, ss, o);
    if (lane == 0) red[warp] = ss;
    __syncthreads();
    if (tid == 0) {
        float t = 0.f;
        #pragma unroll
        for (int i = 0; i < 8; i++) t += red[i];
        red[0] = t;
    }
    __syncthreads();
    float scale = (*gain_p * (1.0f / 32.0f)) / (EPSN + sqrtf(red[0]) * (1.0f / 32.0f));

    float* dst = g_wn + (size_t)mat * (1024u * 1024u) + (size_t)row * EDIM + tid * 4;
    *(float4*)dst = make_float4(to_tf32(w4.x * scale), to_tf32(w4.y * scale),
                                to_tf32(w4.z * scale), to_tf32(w4.w * scale));
}

// ---------------- partial scores (+ fused q/k head-norm) -------------------
// scores[bn,h,k] = sum_s qn[s,h]*kn[s,k]; q,k normalized per (token,head) in smem
// S split into NCHUNK chunks of SEQ/NCHUNK = 256 tokens.
__global__ __launch_bounds__(256)
void scores_part_kernel()
{
    int bn = blockIdx.x;
    int chunk = blockIdx.y;
    int b = bn >> 4, n = bn & 15;

    __shared__ float qs[32][64];
    __shared__ float ks[32][64];

    const float* gq = g_qkv;
    const float* gk = g_qkv + (size_t)TOK * EDIM;

    int tid = threadIdx.x;
    int lane = tid & 31;
    int ty = tid >> 4, tx = tid & 15;

    float acc[4][4];
    #pragma unroll
    for (int i = 0; i < 4; i++)
        #pragma unroll
        for (int j = 0; j < 4; j++) acc[i][j] = 0.f;

    const int CSZ = SEQ / NCHUNK;   // 256
    size_t tbase = ((size_t)b * SEQ + (size_t)chunk * CSZ) * EDIM + n * HDIM;

    for (int s0 = 0; s0 < CSZ; s0 += 32) {
        #pragma unroll
        for (int rr = 0; rr < 2; rr++) {
            int f = tid + rr * 256;
            int r2 = f >> 4;
            int cc = (f & 15) * 4;
            size_t gg = tbase + (size_t)(s0 + r2) * EDIM + cc;
            *(float4*)&qs[r2][cc] = *(const float4*)&gq[gg];
            *(float4*)&ks[r2][cc] = *(const float4*)&gk[gg];
        }
        __syncthreads();

        // fused per-(token,head) normalization: x / (1e-4 + ||x||/8)
        {
            int rowb = (tid >> 5) * 4;        // warp -> 4 rows
            #pragma unroll
            for (int rr = 0; rr < 4; rr++) {
                int row = rowb + rr;
                float qa = qs[row][lane], qb = qs[row][32 + lane];
                float ka = ks[row][lane], kb = ks[row][32 + lane];
                float sq = qa * qa + qb * qb;
                float sk = ka * ka + kb * kb;
                #pragma unroll
                for (int o = 16; o > 0; o >>= 1) {
                    sq += __shfl_xor_sync(0xffffffffu, sq, o);
                    sk += __shfl_xor_sync(0xffffffffu, sk, o);
                }
                float iq = 1.0f / (EPSN + sqrtf(sq) * 0.125f);
                float ik = 1.0f / (EPSN + sqrtf(sk) * 0.125f);
                qs[row][lane] = qa * iq; qs[row][32 + lane] = qb * iq;
                ks[row][lane] = ka * ik; ks[row][32 + lane] = kb * ik;
            }
        }
        __syncthreads();

        #pragma unroll 4
        for (int ss = 0; ss < 32; ss++) {
            float4 q4 = *(const float4*)&qs[ss][ty * 4];
            float4 k4 = *(const float4*)&ks[ss][tx * 4];
            float qa[4] = {q4.x, q4.y, q4.z, q4.w};
            float ka[4] = {k4.x, k4.y, k4.z, k4.w};
            #pragma unroll
            for (int i = 0; i < 4; i++)
                #pragma unroll
                for (int j = 0; j < 4; j++)
                    acc[i][j] = fmaf(qa[i], ka[j], acc[i][j]);
        }
        __syncthreads();
    }

    #pragma unroll
    for (int i = 0; i < 4; i++)
        #pragma unroll
        for (int j = 0; j < 4; j++)
            g_scp[(((size_t)chunk * BH + bn) * HDIM + ty * 4 + i) * HDIM + tx * 4 + j] = acc[i][j];
}

// ---------------- softmax over k (rows of length 64) ------------------------
__global__ __launch_bounds__(256)
void softmax_kernel()
{
    int gw = blockIdx.x * 8 + (threadIdx.x >> 5);
    int lane = threadIdx.x & 31;
    int bn = gw >> 6, h = gw & 63;

    float v0 = 0.f, v1 = 0.f;
    #pragma unroll
    for (int c = 0; c < NCHUNK; c++) {
        size_t o = (((size_t)c * BH + bn) * HDIM + h) * HDIM;
        v0 += g_scp[o + lane];
        v1 += g_scp[o + 32 + lane];
    }
    v0 *= (1.0f / 64.0f);   // 1/sqrt(4096)
    v1 *= (1.0f / 64.0f);

    float m = fmaxf(v0, v1);
    #pragma unroll
    for (int o = 16; o > 0; o >>= 1) m = fmaxf(m, __shfl_xor_sync(0xffffffffu, m, o));
    float e0 = __expf(v0 - m), e1 = __expf(v1 - m);
    float s = e0 + e1;
    #pragma unroll
    for (int o = 16; o > 0; o >>= 1) s += __shfl_xor_sync(0xffffffffu, s, o);
    float inv = 1.0f / s;

    size_t idx = ((size_t)bn * HDIM + h) * HDIM;
    g_attn[idx + lane] = e0 * inv;
    g_attn[idx + 32 + lane] = e1 * inv;
}

// ---------------- apply attention: o[s,h] = sum_k attn[h,k] * v[s,k] --------
__global__ __launch_bounds__(256)
void o_apply_kernel()
{
    int bn = blockIdx.x;
    int st = blockIdx.y;
    int b = bn >> 4, n = bn & 15;

    __shared__ float at[64 * 65];
    __shared__ float vt[64 * 65];

    const float* gv = g_qkv + 2u * (size_t)TOK * EDIM;

    int tid = threadIdx.x;
    size_t abase = (size_t)bn * HDIM * HDIM;
    #pragma unroll
    for (int rr = 0; rr < 16; rr++) {
        int e = tid + rr * 256;
        int h = e >> 6, k = e & 63;
        at[k * 65 + h] = g_attn[abase + e];
    }
    size_t vbase = ((size_t)b * SEQ + (size_t)st * 64) * EDIM + n * HDIM;
    #pragma unroll
    for (int rr = 0; rr < 16; rr++) {
        int e = tid + rr * 256;
        int s = e >> 6, k = e & 63;
        vt[k * 65 + s] = gv[vbase + (size_t)s * EDIM + k];
    }
    __syncthreads();

    int ty = tid >> 4, tx = tid & 15;
    int s0 = ty * 4, h0 = tx * 4;
    float acc[4][4];
    #pragma unroll
    for (int i = 0; i < 4; i++)
        #pragma unroll
        for (int j = 0; j < 4; j++) acc[i][j] = 0.f;

    #pragma unroll 4
    for (int k = 0; k < 64; k++) {
        float av[4], vv[4];
        #pragma unroll
        for (int j = 0; j < 4; j++) av[j] = at[k * 65 + h0 + j];
        #pragma unroll
        for (int i = 0; i < 4; i++) vv[i] = vt[k * 65 + s0 + i];
        #pragma unroll
        for (int i = 0; i < 4; i++)
            #pragma unroll
            for (int j = 0; j < 4; j++)
                acc[i][j] = fmaf(av[j], vv[i], acc[i][j]);
    }

    size_t obase = ((size_t)b * SEQ + (size_t)st * 64) * EDIM + n * HDIM;
    #pragma unroll
    for (int i = 0; i < 4; i++)
        #pragma unroll
        for (int j = 0; j < 4; j++)
            g_o[obase + (size_t)(s0 + i) * EDIM + h0 + j] = to_tf32(acc[i][j]);
}

// ---------------- host launcher --------------------------------------------
extern "C" void kernel_launch(void* const* d_in, const int* in_sizes, int n_in,
                              void* d_out, int out_size)
{
    const float* query = (const float*)d_in[0];
    const float* gain  = (const float*)d_in[1];
    const float* wq    = (const float*)d_in[2];
    const float* wk    = (const float*)d_in[3];
    const float* wv    = (const float*)d_in[4];
    const float* wo    = (const float*)d_in[5];
    float* out = (float*)d_out;

    float *p_wn, *p_qkv, *p_o;
    cudaGetSymbolAddress((void**)&p_wn,  g_wn);
    cudaGetSymbolAddress((void**)&p_qkv, g_qkv);
    cudaGetSymbolAddress((void**)&p_o,   g_o);

    cudaFuncSetAttribute(gemm_tc_kernel,
                         cudaFuncAttributeMaxDynamicSharedMemorySize, GEMM_SMEM_BYTES);

    // 1) normalize weights (tf32-rounded)
    norm_weights_kernel<<<dim3(1024, 4), 256>>>(wq, wk, wv, wo, gain);

    // 2) fused Q/K/V projection: raw fp32 query (HW truncates A to tf32)
    dim3 qkvgrid(3 * EDIM / 128, TOK / 128);   // (24, 128)
    gemm_tc_kernel<<<qkvgrid, 256, GEMM_SMEM_BYTES>>>(query, p_wn, p_qkv, nullptr, 1.0f);

    // 3) partial scores over 16 s-chunks (q/k head-norm fused in smem)
    scores_part_kernel<<<dim3(BH, NCHUNK), 256>>>();

    // 4) reduce + softmax
    softmax_kernel<<<512, 256>>>();

    // 5) apply attention weights to v (writes tf32-rounded)
    o_apply_kernel<<<dim3(BH, 64), 256>>>();

    // 6) output projection + residual mix: (res + proj) * sqrt(0.5)
    dim3 ogrid(EDIM / 128, TOK / 128);         // (8, 128)
    gemm_tc_kernel<<<ogrid, 256, GEMM_SMEM_BYTES>>>(p_o, p_wn + 3u * (1024u * 1024u), out, query, 0.70710678118654752f);
}

// round 11
// speedup vs baseline: 1.3956x; 1.0670x over previous
#include <cuda_runtime.h>
#include <cuda_bf16.h>
#include <cstdint>
#include <cmath>

// Problem constants: B=4, S=4096, E=1024, H=16, hd=64
#define TOK     16384            // B*S
#define EDIM    1024
#define NHEAD   16
#define HDIM    64
#define BH      64               // B*H
#define SEQ     4096
#define EPSN    1e-4f
#define NCHUNK  32               // s-chunks for partial scores

// ---------------- scratch (static device memory; no allocations) -----------
__device__ float g_wn[4u * 1024u * 1024u];                 // concat wq|wk|wv|wo (tf32)
__device__ float g_qkv[3u * (size_t)TOK * EDIM];           // q | k | v outputs
__device__ float g_o[(size_t)TOK * EDIM];                  // attn output
__device__ float g_scp[(size_t)NCHUNK * BH * HDIM * HDIM]; // partial scores (32 MB)
__device__ float g_attn[BH * HDIM * HDIM];                 // softmaxed attn

// ======================= PTX helpers ========================================
__device__ __forceinline__ uint32_t smem_to_u32(const void* p) {
    uint32_t a;
    asm("{ .reg .u64 t; cvta.to.shared.u64 t, %1; cvt.u32.u64 %0, t; }" : "=r"(a) : "l"(p));
    return a;
}
__device__ __forceinline__ float to_tf32(float x) {
    float r;
    asm("cvt.rna.tf32.f32 %0, %1;" : "=f"(r) : "f"(x));
    return r;
}

#define CP_ASYNC16(dst, src) \
    asm volatile("cp.async.cg.shared.global [%0], [%1], 16;" :: "r"(dst), "l"(src))
#define CP_COMMIT()  asm volatile("cp.async.commit_group;" ::: "memory")
#define CP_WAIT1()   asm volatile("cp.async.wait_group 1;" ::: "memory")

// m16n8k8 tf32 MMA (arch-portable; lowers to fallback HMMA on sm_103)
__device__ __forceinline__ void mma_tf32(float* d, const uint32_t* a, const uint32_t* b) {
    asm volatile(
        "mma.sync.aligned.m16n8k8.row.col.f32.tf32.tf32.f32 "
        "{%0,%1,%2,%3}, {%4,%5,%6,%7}, {%8,%9}, {%0,%1,%2,%3};"
        : "+f"(d[0]), "+f"(d[1]), "+f"(d[2]), "+f"(d[3])
        : "r"(a[0]), "r"(a[1]), "r"(a[2]), "r"(a[3]), "r"(b[0]), "r"(b[1]));
}

// ldmatrix x4: four 8x8-b16 matrices == four 8x4-tf32 fragments
__device__ __forceinline__ void ldsm_x4(uint32_t& r0, uint32_t& r1, uint32_t& r2,
                                        uint32_t& r3, uint32_t addr) {
    asm volatile("ldmatrix.sync.aligned.m8n8.x4.shared.b16 {%0,%1,%2,%3}, [%4];"
                 : "=r"(r0), "=r"(r1), "=r"(r2), "=r"(r3) : "r"(addr));
}

// ======================= tf32 mma.sync GEMM =================================
// C[row, col_global] = sum_k A[row,k] * B[col_global,k]
// QKV fused: grid.x=24 routes cols to q|k|v thirds; others: grid.x=8, mat=0.
// 128x128 CTA tile, K-chunk 32, 3-stage cp.async, one barrier per chunk.
// A operand may be raw fp32: HW truncates to tf32 inside the MMA.
#define PADW   36                       // floats per smem row (32 + 4 pad)
#define STAGEF (128 * PADW)             // 4608 floats per matrix per stage
#define GEMM_SMEM_BYTES (6 * STAGEF * 4)  // A:3 + B:3 stages = 110592

__global__ __launch_bounds__(256, 2)
void gemm_tc_kernel(const float* __restrict__ A, const float* __restrict__ B,
                    float* __restrict__ C, const float* __restrict__ Res, float alpha)
{
    extern __shared__ __align__(16) float smem[];
    float* sA0 = smem;                  // 3 stages of A
    float* sB0 = smem + 3 * STAGEF;     // 3 stages of B
    const uint32_t sbaseA = smem_to_u32(sA0);
    const uint32_t sbaseB = smem_to_u32(sB0);

    const int tid = threadIdx.x;
    const int wid = tid >> 5;
    const int lane = tid & 31;
    const int g = lane >> 2;            // group id 0..7
    const int tig = lane & 3;           // thread-in-group 0..3
    const int m0 = (wid >> 2) * 64;     // warp M offset in tile
    const int n0 = (wid & 3) * 32;      // warp N offset in tile
    const int bm = blockIdx.y * 128;
    const int bn = blockIdx.x * 128;    // global col base (may exceed 1024 in QKV mode)

    // output matrix routing (tile never straddles a 1024 boundary)
    const int mat = bn >> 10;
    const int bnl = bn & 1023;          // col base within the output matrix
    float* Cbase = C + (size_t)mat * ((size_t)TOK * EDIM);

    // ldmatrix per-lane address offsets (in floats); q = lane>>3, r = lane&7
    const int q = lane >> 3, r = lane & 7;
    const int laneA = ((q & 1) * 8 + r) * PADW + (q >> 1) * 4;
    const int laneB = ((q >> 1) * 8 + r) * PADW + (q & 1) * 4;

    const char* gA = (const char*)(A + (size_t)bm * EDIM);
    const char* gB = (const char*)(B + (size_t)bn * EDIM);

    // loader: one K-chunk (128 rows x 32 floats) of A and B into stage st
    auto load_chunk = [&](int kc, int st) {
        uint32_t dA = sbaseA + (uint32_t)st * (STAGEF * 4);
        uint32_t dB = sbaseB + (uint32_t)st * (STAGEF * 4);
        int koff = kc * 128;                 // byte offset of chunk within row
        #pragma unroll
        for (int rr = 0; rr < 4; rr++) {
            int f = tid + rr * 256;          // 0..1023 float4 slots
            int row = f >> 3;                // 0..127
            int seg = (f & 7) * 16;          // byte seg within chunk row
            uint32_t so = (uint32_t)(row * (PADW * 4) + seg);
            size_t  go = (size_t)row * (EDIM * 4) + koff + seg;
            CP_ASYNC16(dA + so, gA + go);
            CP_ASYNC16(dB + so, gB + go);
        }
    };

    float acc[4][4][4];
    #pragma unroll
    for (int i = 0; i < 4; i++)
        #pragma unroll
        for (int j = 0; j < 4; j++)
            #pragma unroll
            for (int c = 0; c < 4; c++) acc[i][j][c] = 0.f;

    load_chunk(0, 0); CP_COMMIT();
    load_chunk(1, 1); CP_COMMIT();

    for (int c = 0; c < 32; c++) {
        CP_WAIT1();
        __syncthreads();   // chunk c visible; all warps done reading stage (c-1)%3

        if (c + 2 < 32) load_chunk(c + 2, (c + 2) % 3);
        CP_COMMIT();                      // always commit (possibly empty group)

        const uint32_t stA = sbaseA + (uint32_t)(c % 3) * (STAGEF * 4);
        const uint32_t stB = sbaseB + (uint32_t)(c % 3) * (STAGEF * 4);
        const uint32_t aBase = stA + (uint32_t)((m0 * PADW + laneA) * 4);
        const uint32_t bBase = stB + (uint32_t)((n0 * PADW + laneB) * 4);

        #pragma unroll
        for (int ks = 0; ks < 4; ks++) {
            uint32_t a[4][4];
            #pragma unroll
            for (int i = 0; i < 4; i++)
                ldsm_x4(a[i][0], a[i][1], a[i][2], a[i][3],
                        aBase + (uint32_t)(i * (16 * PADW * 4) + ks * 32));
            uint32_t b[4][2];
            #pragma unroll
            for (int jp = 0; jp < 2; jp++)
                ldsm_x4(b[jp * 2][0], b[jp * 2][1], b[jp * 2 + 1][0], b[jp * 2 + 1][1],
                        bBase + (uint32_t)(jp * (16 * PADW * 4) + ks * 32));
            #pragma unroll
            for (int i = 0; i < 4; i++)
                #pragma unroll
                for (int j = 0; j < 4; j++)
                    mma_tf32(acc[i][j], a[i], b[j]);
        }
    }

    #pragma unroll
    for (int i = 0; i < 4; i++) {
        int row = bm + m0 + 16 * i + g;
        #pragma unroll
        for (int j = 0; j < 4; j++) {
            int col = bnl + n0 + 8 * j + tig * 2;
            float2 v0 = make_float2(acc[i][j][0], acc[i][j][1]);
            float2 v1 = make_float2(acc[i][j][2], acc[i][j][3]);
            if (Res != nullptr) {
                float2 r0 = *(const float2*)(Res + (size_t)row * EDIM + col);
                float2 r1 = *(const float2*)(Res + (size_t)(row + 8) * EDIM + col);
                v0.x = (v0.x + r0.x) * alpha; v0.y = (v0.y + r0.y) * alpha;
                v1.x = (v1.x + r1.x) * alpha; v1.y = (v1.y + r1.y) * alpha;
            }
            *(float2*)(Cbase + (size_t)row * EDIM + col) = v0;
            *(float2*)(Cbase + (size_t)(row + 8) * EDIM + col) = v1;
        }
    }
}

// ---------------- magnitude-preserving weight normalization (-> tf32) ------
__global__ __launch_bounds__(256)
void norm_weights_kernel(const float* __restrict__ wq, const float* __restrict__ wk,
                         const float* __restrict__ wv, const float* __restrict__ wo,
                         const float* __restrict__ gain_p)
{
    int row = blockIdx.x;
    int mat = blockIdx.y;
    const float* W = (mat == 0) ? wq : (mat == 1) ? wk : (mat == 2) ? wv : wo;
    const float* src = W + (size_t)row * EDIM;

    int tid = threadIdx.x;
    float4 w4 = *(const float4*)(src + tid * 4);
    float ss = w4.x * w4.x + w4.y * w4.y + w4.z * w4.z + w4.w * w4.w;

    __shared__ float red[8];
    int lane = tid & 31, warp = tid >> 5;
    #pragma unroll
    for (int o = 16; o > 0; o >>= 1) ss += __shfl_xor_sync(0xffffffffu, ss, o);
    if (lane == 0) red[warp] = ss;
    __syncthreads();
    if (tid == 0) {
        float t = 0.f;
        #pragma unroll
        for (int i = 0; i < 8; i++) t += red[i];
        red[0] = t;
    }
    __syncthreads();
    float scale = (*gain_p * (1.0f / 32.0f)) / (EPSN + sqrtf(red[0]) * (1.0f / 32.0f));

    float* dst = g_wn + (size_t)mat * (1024u * 1024u) + (size_t)row * EDIM + tid * 4;
    *(float4*)dst = make_float4(to_tf32(w4.x * scale), to_tf32(w4.y * scale),
                                to_tf32(w4.z * scale), to_tf32(w4.w * scale));
}

// ---------------- partial scores (+ fused q/k head-norm) -------------------
// scores[bn,h,k] = sum_s qn[s,h]*kn[s,k]; S split into NCHUNK chunks.
__global__ __launch_bounds__(256)
void scores_part_kernel()
{
    int bn = blockIdx.x;
    int chunk = blockIdx.y;
    int b = bn >> 4, n = bn & 15;

    __shared__ float qs[32][64];
    __shared__ float ks[32][64];

    const float* gq = g_qkv;
    const float* gk = g_qkv + (size_t)TOK * EDIM;

    int tid = threadIdx.x;
    int lane = tid & 31;
    int ty = tid >> 4, tx = tid & 15;

    float acc[4][4];
    #pragma unroll
    for (int i = 0; i < 4; i++)
        #pragma unroll
        for (int j = 0; j < 4; j++) acc[i][j] = 0.f;

    const int CSZ = SEQ / NCHUNK;   // 128
    size_t tbase = ((size_t)b * SEQ + (size_t)chunk * CSZ) * EDIM + n * HDIM;

    for (int s0 = 0; s0 < CSZ; s0 += 32) {
        #pragma unroll
        for (int rr = 0; rr < 2; rr++) {
            int f = tid + rr * 256;
            int r2 = f >> 4;
            int cc = (f & 15) * 4;
            size_t gg = tbase + (size_t)(s0 + r2) * EDIM + cc;
            *(float4*)&qs[r2][cc] = *(const float4*)&gq[gg];
            *(float4*)&ks[r2][cc] = *(const float4*)&gk[gg];
        }
        __syncthreads();

        // fused per-(token,head) normalization: x / (1e-4 + ||x||/8)
        {
            int rowb = (tid >> 5) * 4;        // warp -> 4 rows
            #pragma unroll
            for (int rr = 0; rr < 4; rr++) {
                int row = rowb + rr;
                float qa = qs[row][lane], qb = qs[row][32 + lane];
                float ka = ks[row][lane], kb = ks[row][32 + lane];
                float sq = qa * qa + qb * qb;
                float sk = ka * ka + kb * kb;
                #pragma unroll
                for (int o = 16; o > 0; o >>= 1) {
                    sq += __shfl_xor_sync(0xffffffffu, sq, o);
                    sk += __shfl_xor_sync(0xffffffffu, sk, o);
                }
                float iq = 1.0f / (EPSN + sqrtf(sq) * 0.125f);
                float ik = 1.0f / (EPSN + sqrtf(sk) * 0.125f);
                qs[row][lane] = qa * iq; qs[row][32 + lane] = qb * iq;
                ks[row][lane] = ka * ik; ks[row][32 + lane] = kb * ik;
            }
        }
        __syncthreads();

        #pragma unroll 4
        for (int ss = 0; ss < 32; ss++) {
            float4 q4 = *(const float4*)&qs[ss][ty * 4];
            float4 k4 = *(const float4*)&ks[ss][tx * 4];
            float qa[4] = {q4.x, q4.y, q4.z, q4.w};
            float ka[4] = {k4.x, k4.y, k4.z, k4.w};
            #pragma unroll
            for (int i = 0; i < 4; i++)
                #pragma unroll
                for (int j = 0; j < 4; j++)
                    acc[i][j] = fmaf(qa[i], ka[j], acc[i][j]);
        }
        __syncthreads();
    }

    #pragma unroll
    for (int i = 0; i < 4; i++)
        #pragma unroll
        for (int j = 0; j < 4; j++)
            g_scp[(((size_t)chunk * BH + bn) * HDIM + ty * 4 + i) * HDIM + tx * 4 + j] = acc[i][j];
}

// ---------------- softmax over k (rows of length 64) ------------------------
__global__ __launch_bounds__(256)
void softmax_kernel()
{
    int gw = blockIdx.x * 8 + (threadIdx.x >> 5);
    int lane = threadIdx.x & 31;
    int bn = gw >> 6, h = gw & 63;

    float v0 = 0.f, v1 = 0.f;
    #pragma unroll
    for (int c = 0; c < NCHUNK; c++) {
        size_t o = (((size_t)c * BH + bn) * HDIM + h) * HDIM;
        v0 += g_scp[o + lane];
        v1 += g_scp[o + 32 + lane];
    }
    v0 *= (1.0f / 64.0f);   // 1/sqrt(4096)
    v1 *= (1.0f / 64.0f);

    float m = fmaxf(v0, v1);
    #pragma unroll
    for (int o = 16; o > 0; o >>= 1) m = fmaxf(m, __shfl_xor_sync(0xffffffffu, m, o));
    float e0 = __expf(v0 - m), e1 = __expf(v1 - m);
    float s = e0 + e1;
    #pragma unroll
    for (int o = 16; o > 0; o >>= 1) s += __shfl_xor_sync(0xffffffffu, s, o);
    float inv = 1.0f / s;

    size_t idx = ((size_t)bn * HDIM + h) * HDIM;
    g_attn[idx + lane] = e0 * inv;
    g_attn[idx + 32 + lane] = e1 * inv;
}

// ---------------- apply attention (tensor cores) ----------------------------
// o[s,h] = sum_k attn[h,k] * v[s,k]  ==  V[s,k] · ATTN[h,k]^T  (m16n8k8 NT form)
// Block: one (b,head) x 128-token tile. M=128(s), N=64(hd), K=64.
#define OPAD 68   // 64 + 4 pad floats per smem row (4r mod 32 bank walk, conflict-free)
__global__ __launch_bounds__(256)
void o_apply_tc_kernel()
{
    int bn = blockIdx.x;          // 0..63
    int st = blockIdx.y;          // 0..31 (128-token tile)
    int b = bn >> 4, n = bn & 15;

    __shared__ __align__(16) float sv[128 * OPAD];   // v tile  [s][k]
    __shared__ __align__(16) float sa[64 * OPAD];    // attn    [h][k]

    const float* gv = g_qkv + 2u * (size_t)TOK * EDIM;

    int tid = threadIdx.x;
    int wid = tid >> 5;
    int lane = tid & 31;
    int g = lane >> 2;
    int tig = lane & 3;

    // load attn tile: 4096 floats, coalesced
    size_t abase = (size_t)bn * HDIM * HDIM;
    #pragma unroll
    for (int rr = 0; rr < 4; rr++) {
        int f = tid + rr * 256;           // float4 slot 0..1023
        int h = f >> 4;
        int c4 = (f & 15) * 4;
        *(float4*)&sa[h * OPAD + c4] = *(const float4*)&g_attn[abase + h * HDIM + c4];
    }
    // load v tile: 128 rows x 64 floats
    size_t vbase = ((size_t)b * SEQ + (size_t)st * 128) * EDIM + n * HDIM;
    #pragma unroll
    for (int rr = 0; rr < 8; rr++) {
        int f = tid + rr * 256;           // float4 slot 0..2047
        int row = f >> 4;
        int c4 = (f & 15) * 4;
        *(float4*)&sv[row * OPAD + c4] = *(const float4*)&gv[vbase + (size_t)row * EDIM + c4];
    }
    __syncthreads();

    // 8 warps = 4(M) x 2(N); warp tile 32(s) x 32(hd); frags 2(M) x 4(N), 8 k-steps
    int m0 = (wid & 3) * 32;
    int n0 = (wid >> 2) * 32;
    const uint32_t svb = smem_to_u32(sv);
    const uint32_t sab = smem_to_u32(sa);
    int q = lane >> 3, r = lane & 7;
    const uint32_t aBase = svb + (uint32_t)((m0 * OPAD + ((q & 1) * 8 + r) * OPAD + (q >> 1) * 4) * 4);
    const uint32_t bBase = sab + (uint32_t)((n0 * OPAD + ((q >> 1) * 8 + r) * OPAD + (q & 1) * 4) * 4);

    float acc[2][4][4];
    #pragma unroll
    for (int i = 0; i < 2; i++)
        #pragma unroll
        for (int j = 0; j < 4; j++)
            #pragma unroll
            for (int c = 0; c < 4; c++) acc[i][j][c] = 0.f;

    #pragma unroll
    for (int ks = 0; ks < 8; ks++) {
        uint32_t a[2][4];
        #pragma unroll
        for (int i = 0; i < 2; i++)
            ldsm_x4(a[i][0], a[i][1], a[i][2], a[i][3],
                    aBase + (uint32_t)(i * (16 * OPAD * 4) + ks * 32));
        uint32_t bfr[4][2];
        #pragma unroll
        for (int jp = 0; jp < 2; jp++)
            ldsm_x4(bfr[jp * 2][0], bfr[jp * 2][1], bfr[jp * 2 + 1][0], bfr[jp * 2 + 1][1],
                    bBase + (uint32_t)(jp * (16 * OPAD * 4) + ks * 32));
        #pragma unroll
        for (int i = 0; i < 2; i++)
            #pragma unroll
            for (int j = 0; j < 4; j++)
                mma_tf32(acc[i][j], a[i], bfr[j]);
    }

    // epilogue: write o[token, n*64 + col]
    size_t obase = ((size_t)b * SEQ + (size_t)st * 128) * EDIM + n * HDIM;
    #pragma unroll
    for (int i = 0; i < 2; i++) {
        int srow = m0 + 16 * i + g;
        #pragma unroll
        for (int j = 0; j < 4; j++) {
            int col = n0 + 8 * j + tig * 2;
            *(float2*)&g_o[obase + (size_t)srow * EDIM + col] =
                make_float2(acc[i][j][0], acc[i][j][1]);
            *(float2*)&g_o[obase + (size_t)(srow + 8) * EDIM + col] =
                make_float2(acc[i][j][2], acc[i][j][3]);
        }
    }
}

// ---------------- host launcher --------------------------------------------
extern "C" void kernel_launch(void* const* d_in, const int* in_sizes, int n_in,
                              void* d_out, int out_size)
{
    const float* query = (const float*)d_in[0];
    const float* gain  = (const float*)d_in[1];
    const float* wq    = (const float*)d_in[2];
    const float* wk    = (const float*)d_in[3];
    const float* wv    = (const float*)d_in[4];
    const float* wo    = (const float*)d_in[5];
    float* out = (float*)d_out;

    float *p_wn, *p_qkv, *p_o;
    cudaGetSymbolAddress((void**)&p_wn,  g_wn);
    cudaGetSymbolAddress((void**)&p_qkv, g_qkv);
    cudaGetSymbolAddress((void**)&p_o,   g_o);

    cudaFuncSetAttribute(gemm_tc_kernel,
                         cudaFuncAttributeMaxDynamicSharedMemorySize, GEMM_SMEM_BYTES);

    // 1) normalize weights (tf32-rounded)
    norm_weights_kernel<<<dim3(1024, 4), 256>>>(wq, wk, wv, wo, gain);

    // 2) fused Q/K/V projection: raw fp32 query (HW truncates A to tf32)
    dim3 qkvgrid(3 * EDIM / 128, TOK / 128);   // (24, 128)
    gemm_tc_kernel<<<qkvgrid, 256, GEMM_SMEM_BYTES>>>(query, p_wn, p_qkv, nullptr, 1.0f);

    // 3) partial scores over 32 s-chunks (q/k head-norm fused in smem)
    scores_part_kernel<<<dim3(BH, NCHUNK), 256>>>();

    // 4) reduce + softmax
    softmax_kernel<<<512, 256>>>();

    // 5) apply attention weights to v (tensor cores)
    o_apply_tc_kernel<<<dim3(BH, 32), 256>>>();

    // 6) output projection + residual mix: (res + proj) * sqrt(0.5)
    dim3 ogrid(EDIM / 128, TOK / 128);         // (8, 128)
    gemm_tc_kernel<<<ogrid, 256, GEMM_SMEM_BYTES>>>(p_o, p_wn + 3u * (1024u * 1024u), out, query, 0.70710678118654752f);
}

// round 12
// speedup vs baseline: 1.4470x; 1.0369x over previous
#include <cuda_runtime.h>
#include <cuda_bf16.h>
#include <cstdint>
#include <cmath>

// Problem constants: B=4, S=4096, E=1024, H=16, hd=64
#define TOK     16384            // B*S
#define EDIM    1024
#define NHEAD   16
#define HDIM    64
#define BH      64               // B*H
#define SEQ     4096
#define EPSN    1e-4f
#define NCHUNK  32               // s-chunks for partial scores

// ---------------- scratch (static device memory; no allocations) -----------
__device__ float g_wn[4u * 1024u * 1024u];                 // concat wq|wk|wv|wo (tf32)
__device__ float g_qkv[3u * (size_t)TOK * EDIM];           // q | k | v outputs
__device__ float g_o[(size_t)TOK * EDIM];                  // attn output
__device__ float g_scp[(size_t)NCHUNK * BH * HDIM * HDIM]; // partial scores (32 MB)
__device__ float g_attn[BH * HDIM * HDIM];                 // softmaxed attn

// ======================= PTX helpers ========================================
__device__ __forceinline__ uint32_t smem_to_u32(const void* p) {
    uint32_t a;
    asm("{ .reg .u64 t; cvta.to.shared.u64 t, %1; cvt.u32.u64 %0, t; }" : "=r"(a) : "l"(p));
    return a;
}
__device__ __forceinline__ float to_tf32(float x) {
    float r;
    asm("cvt.rna.tf32.f32 %0, %1;" : "=f"(r) : "f"(x));
    return r;
}

#define CP_ASYNC16(dst, src) \
    asm volatile("cp.async.cg.shared.global [%0], [%1], 16;" :: "r"(dst), "l"(src))
#define CP_COMMIT()  asm volatile("cp.async.commit_group;" ::: "memory")
#define CP_WAIT1()   asm volatile("cp.async.wait_group 1;" ::: "memory")

// m16n8k8 tf32 MMA (arch-portable; lowers to fallback HMMA on sm_103)
__device__ __forceinline__ void mma_tf32(float* d, const uint32_t* a, const uint32_t* b) {
    asm volatile(
        "mma.sync.aligned.m16n8k8.row.col.f32.tf32.tf32.f32 "
        "{%0,%1,%2,%3}, {%4,%5,%6,%7}, {%8,%9}, {%0,%1,%2,%3};"
        : "+f"(d[0]), "+f"(d[1]), "+f"(d[2]), "+f"(d[3])
        : "r"(a[0]), "r"(a[1]), "r"(a[2]), "r"(a[3]), "r"(b[0]), "r"(b[1]));
}

// ldmatrix x4: four 8x8-b16 matrices == four 8x4-tf32 fragments
__device__ __forceinline__ void ldsm_x4(uint32_t& r0, uint32_t& r1, uint32_t& r2,
                                        uint32_t& r3, uint32_t addr) {
    asm volatile("ldmatrix.sync.aligned.m8n8.x4.shared.b16 {%0,%1,%2,%3}, [%4];"
                 : "=r"(r0), "=r"(r1), "=r"(r2), "=r"(r3) : "r"(addr));
}

// ======================= tf32 mma.sync GEMM =================================
// C[row, col_global] = sum_k A[row,k] * B[col_global,k]
// QKV fused: grid.x=24 routes cols to q|k|v thirds; others: grid.x=8, mat=0.
// 128x128 CTA tile, K-chunk 32, 3-stage cp.async, one barrier per chunk.
#define PADW   36                       // floats per smem row (32 + 4 pad)
#define STAGEF (128 * PADW)             // 4608 floats per matrix per stage
#define GEMM_SMEM_BYTES (6 * STAGEF * 4)  // A:3 + B:3 stages = 110592

__global__ __launch_bounds__(256, 2)
void gemm_tc_kernel(const float* __restrict__ A, const float* __restrict__ B,
                    float* __restrict__ C, const float* __restrict__ Res, float alpha)
{
    extern __shared__ __align__(16) float smem[];
    float* sA0 = smem;                  // 3 stages of A
    float* sB0 = smem + 3 * STAGEF;     // 3 stages of B
    const uint32_t sbaseA = smem_to_u32(sA0);
    const uint32_t sbaseB = smem_to_u32(sB0);

    const int tid = threadIdx.x;
    const int wid = tid >> 5;
    const int lane = tid & 31;
    const int g = lane >> 2;            // group id 0..7
    const int tig = lane & 3;           // thread-in-group 0..3
    const int m0 = (wid >> 2) * 64;     // warp M offset in tile
    const int n0 = (wid & 3) * 32;      // warp N offset in tile
    const int bm = blockIdx.y * 128;
    const int bn = blockIdx.x * 128;    // global col base (may exceed 1024 in QKV mode)

    const int mat = bn >> 10;
    const int bnl = bn & 1023;          // col base within the output matrix
    float* Cbase = C + (size_t)mat * ((size_t)TOK * EDIM);

    const int q = lane >> 3, r = lane & 7;
    const int laneA = ((q & 1) * 8 + r) * PADW + (q >> 1) * 4;
    const int laneB = ((q >> 1) * 8 + r) * PADW + (q & 1) * 4;

    const char* gA = (const char*)(A + (size_t)bm * EDIM);
    const char* gB = (const char*)(B + (size_t)bn * EDIM);

    auto load_chunk = [&](int kc, int st) {
        uint32_t dA = sbaseA + (uint32_t)st * (STAGEF * 4);
        uint32_t dB = sbaseB + (uint32_t)st * (STAGEF * 4);
        int koff = kc * 128;                 // byte offset of chunk within row
        #pragma unroll
        for (int rr = 0; rr < 4; rr++) {
            int f = tid + rr * 256;          // 0..1023 float4 slots
            int row = f >> 3;                // 0..127
            int seg = (f & 7) * 16;          // byte seg within chunk row
            uint32_t so = (uint32_t)(row * (PADW * 4) + seg);
            size_t  go = (size_t)row * (EDIM * 4) + koff + seg;
            CP_ASYNC16(dA + so, gA + go);
            CP_ASYNC16(dB + so, gB + go);
        }
    };

    float acc[4][4][4];
    #pragma unroll
    for (int i = 0; i < 4; i++)
        #pragma unroll
        for (int j = 0; j < 4; j++)
            #pragma unroll
            for (int c = 0; c < 4; c++) acc[i][j][c] = 0.f;

    load_chunk(0, 0); CP_COMMIT();
    load_chunk(1, 1); CP_COMMIT();

    for (int c = 0; c < 32; c++) {
        CP_WAIT1();
        __syncthreads();   // chunk c visible; all warps done reading stage (c-1)%3

        if (c + 2 < 32) load_chunk(c + 2, (c + 2) % 3);
        CP_COMMIT();                      // always commit (possibly empty group)

        const uint32_t stA = sbaseA + (uint32_t)(c % 3) * (STAGEF * 4);
        const uint32_t stB = sbaseB + (uint32_t)(c % 3) * (STAGEF * 4);
        const uint32_t aBase = stA + (uint32_t)((m0 * PADW + laneA) * 4);
        const uint32_t bBase = stB + (uint32_t)((n0 * PADW + laneB) * 4);

        #pragma unroll
        for (int ks = 0; ks < 4; ks++) {
            uint32_t a[4][4];
            #pragma unroll
            for (int i = 0; i < 4; i++)
                ldsm_x4(a[i][0], a[i][1], a[i][2], a[i][3],
                        aBase + (uint32_t)(i * (16 * PADW * 4) + ks * 32));
            uint32_t b[4][2];
            #pragma unroll
            for (int jp = 0; jp < 2; jp++)
                ldsm_x4(b[jp * 2][0], b[jp * 2][1], b[jp * 2 + 1][0], b[jp * 2 + 1][1],
                        bBase + (uint32_t)(jp * (16 * PADW * 4) + ks * 32));
            #pragma unroll
            for (int i = 0; i < 4; i++)
                #pragma unroll
                for (int j = 0; j < 4; j++)
                    mma_tf32(acc[i][j], a[i], b[j]);
        }
    }

    #pragma unroll
    for (int i = 0; i < 4; i++) {
        int row = bm + m0 + 16 * i + g;
        #pragma unroll
        for (int j = 0; j < 4; j++) {
            int col = bnl + n0 + 8 * j + tig * 2;
            float2 v0 = make_float2(acc[i][j][0], acc[i][j][1]);
            float2 v1 = make_float2(acc[i][j][2], acc[i][j][3]);
            if (Res != nullptr) {
                float2 r0 = *(const float2*)(Res + (size_t)row * EDIM + col);
                float2 r1 = *(const float2*)(Res + (size_t)(row + 8) * EDIM + col);
                v0.x = (v0.x + r0.x) * alpha; v0.y = (v0.y + r0.y) * alpha;
                v1.x = (v1.x + r1.x) * alpha; v1.y = (v1.y + r1.y) * alpha;
            }
            *(float2*)(Cbase + (size_t)row * EDIM + col) = v0;
            *(float2*)(Cbase + (size_t)(row + 8) * EDIM + col) = v1;
        }
    }
}

// ---------------- magnitude-preserving weight normalization (-> tf32) ------
__global__ __launch_bounds__(256)
void norm_weights_kernel(const float* __restrict__ wq, const float* __restrict__ wk,
                         const float* __restrict__ wv, const float* __restrict__ wo,
                         const float* __restrict__ gain_p)
{
    int row = blockIdx.x;
    int mat = blockIdx.y;
    const float* W = (mat == 0) ? wq : (mat == 1) ? wk : (mat == 2) ? wv : wo;
    const float* src = W + (size_t)row * EDIM;

    int tid = threadIdx.x;
    float4 w4 = *(const float4*)(src + tid * 4);
    float ss = w4.x * w4.x + w4.y * w4.y + w4.z * w4.z + w4.w * w4.w;

    __shared__ float red[8];
    int lane = tid & 31, warp = tid >> 5;
    #pragma unroll
    for (int o = 16; o > 0; o >>= 1) ss += __shfl_xor_sync(0xffffffffu, ss, o);
    if (lane == 0) red[warp] = ss;
    __syncthreads();
    if (tid == 0) {
        float t = 0.f;
        #pragma unroll
        for (int i = 0; i < 8; i++) t += red[i];
        red[0] = t;
    }
    __syncthreads();
    float scale = (*gain_p * (1.0f / 32.0f)) / (EPSN + sqrtf(red[0]) * (1.0f / 32.0f));

    float* dst = g_wn + (size_t)mat * (1024u * 1024u) + (size_t)row * EDIM + tid * 4;
    *(float4*)dst = make_float4(to_tf32(w4.x * scale), to_tf32(w4.y * scale),
                                to_tf32(w4.z * scale), to_tf32(w4.w * scale));
}

// ---------------- partial scores on tensor cores (+ fused q/k head-norm) ---
// scores[bn,h,k] = sum_s qn[s,h]*kn[s,k]; S split into NCHUNK chunks of 128.
// q,k normalized per (token,head) in registers, written TRANSPOSED (RNA tf32)
// to smem [h][s] / [k][s]; m16n8k8 fragments via direct LDS (banks 4g+tig).
#define SPAD 36
__global__ __launch_bounds__(256)
void scores_part_tc_kernel()
{
    int bn = blockIdx.x;      // 0..63
    int chunk = blockIdx.y;   // 0..NCHUNK-1
    int b = bn >> 4, n = bn & 15;

    __shared__ __align__(16) float stq[64 * SPAD];   // q^T: [h][s], s-tile of 32
    __shared__ __align__(16) float stk[64 * SPAD];   // k^T: [k][s]

    const float* gq = g_qkv;
    const float* gk = g_qkv + (size_t)TOK * EDIM;

    int tid = threadIdx.x, wid = tid >> 5, lane = tid & 31;
    int g = lane >> 2, tig = lane & 3;

    // warp MMA tile: 4(m) x 2(n) warps; warp = 16(h) x 32(k)
    int m0 = (wid & 3) * 16;
    int n0 = (wid >> 2) * 32;

    float acc[4][4];   // 4 n-frags x 4 regs
    #pragma unroll
    for (int j = 0; j < 4; j++)
        #pragma unroll
        for (int c = 0; c < 4; c++) acc[j][c] = 0.f;

    const int CSZ = SEQ / NCHUNK;   // 128
    size_t tokbase = (size_t)b * SEQ + (size_t)chunk * CSZ;

    for (int s0 = 0; s0 < CSZ; s0 += 32) {
        // load + norm + transpose: warp wid handles s-rows wid*4 .. wid*4+3
        #pragma unroll
        for (int rr = 0; rr < 4; rr++) {
            int srow = wid * 4 + rr;           // 0..31 within tile
            size_t goff = (tokbase + s0 + srow) * EDIM + (size_t)n * HDIM;
            float qa = gq[goff + lane], qb = gq[goff + 32 + lane];
            float ka = gk[goff + lane], kb = gk[goff + 32 + lane];
            float sq = qa * qa + qb * qb;
            float sk = ka * ka + kb * kb;
            #pragma unroll
            for (int o = 16; o > 0; o >>= 1) {
                sq += __shfl_xor_sync(0xffffffffu, sq, o);
                sk += __shfl_xor_sync(0xffffffffu, sk, o);
            }
            float iq = 1.0f / (EPSN + sqrtf(sq) * 0.125f);
            float ik = 1.0f / (EPSN + sqrtf(sk) * 0.125f);
            stq[lane * SPAD + srow]        = to_tf32(qa * iq);
            stq[(lane + 32) * SPAD + srow] = to_tf32(qb * iq);
            stk[lane * SPAD + srow]        = to_tf32(ka * ik);
            stk[(lane + 32) * SPAD + srow] = to_tf32(kb * ik);
        }
        __syncthreads();

        // 4 k-steps of m16n8k8 over the 32-s tile
        #pragma unroll
        for (int ks = 0; ks < 4; ks++) {
            int kc = ks * 8 + tig;
            uint32_t a[4];
            a[0] = __float_as_uint(stq[(m0 + g) * SPAD + kc]);
            a[1] = __float_as_uint(stq[(m0 + g + 8) * SPAD + kc]);
            a[2] = __float_as_uint(stq[(m0 + g) * SPAD + kc + 4]);
            a[3] = __float_as_uint(stq[(m0 + g + 8) * SPAD + kc + 4]);
            #pragma unroll
            for (int j = 0; j < 4; j++) {
                uint32_t bf[2];
                bf[0] = __float_as_uint(stk[(n0 + 8 * j + g) * SPAD + kc]);
                bf[1] = __float_as_uint(stk[(n0 + 8 * j + g) * SPAD + kc + 4]);
                mma_tf32(acc[j], a, bf);
            }
        }
        __syncthreads();   // before next tile overwrites smem
    }

    // write partial scores: rows h = m0+g (+8), cols k = n0+8j+tig*2 (+1)
    size_t base = ((size_t)chunk * BH + bn) * (HDIM * HDIM);
    #pragma unroll
    for (int j = 0; j < 4; j++) {
        int kcol = n0 + 8 * j + tig * 2;
        *(float2*)&g_scp[base + (size_t)(m0 + g) * HDIM + kcol] =
            make_float2(acc[j][0], acc[j][1]);
        *(float2*)&g_scp[base + (size_t)(m0 + g + 8) * HDIM + kcol] =
            make_float2(acc[j][2], acc[j][3]);
    }
}

// ---------------- softmax over k (rows of length 64) ------------------------
__global__ __launch_bounds__(256)
void softmax_kernel()
{
    int gw = blockIdx.x * 8 + (threadIdx.x >> 5);
    int lane = threadIdx.x & 31;
    int bn = gw >> 6, h = gw & 63;

    float v0 = 0.f, v1 = 0.f;
    #pragma unroll
    for (int c = 0; c < NCHUNK; c++) {
        size_t o = (((size_t)c * BH + bn) * HDIM + h) * HDIM;
        v0 += g_scp[o + lane];
        v1 += g_scp[o + 32 + lane];
    }
    v0 *= (1.0f / 64.0f);   // 1/sqrt(4096)
    v1 *= (1.0f / 64.0f);

    float m = fmaxf(v0, v1);
    #pragma unroll
    for (int o = 16; o > 0; o >>= 1) m = fmaxf(m, __shfl_xor_sync(0xffffffffu, m, o));
    float e0 = __expf(v0 - m), e1 = __expf(v1 - m);
    float s = e0 + e1;
    #pragma unroll
    for (int o = 16; o > 0; o >>= 1) s += __shfl_xor_sync(0xffffffffu, s, o);
    float inv = 1.0f / s;

    size_t idx = ((size_t)bn * HDIM + h) * HDIM;
    g_attn[idx + lane] = e0 * inv;
    g_attn[idx + 32 + lane] = e1 * inv;
}

// ---------------- apply attention (tensor cores, RNA-rounded operands) ------
// o[s,h] = sum_k attn[h,k] * v[s,k]  ==  V[s,k] · ATTN[h,k]^T
#define OPAD 68
__global__ __launch_bounds__(256)
void o_apply_tc_kernel()
{
    int bn = blockIdx.x;          // 0..63
    int st = blockIdx.y;          // 0..31 (128-token tile)
    int b = bn >> 4, n = bn & 15;

    __shared__ __align__(16) float sv[128 * OPAD];   // v tile  [s][k]
    __shared__ __align__(16) float sa[64 * OPAD];    // attn    [h][k]

    const float* gv = g_qkv + 2u * (size_t)TOK * EDIM;

    int tid = threadIdx.x;
    int wid = tid >> 5;
    int lane = tid & 31;
    int g = lane >> 2;
    int tig = lane & 3;

    // load attn tile (RNA-round to tf32 to avoid biased HW truncation)
    size_t abase = (size_t)bn * HDIM * HDIM;
    #pragma unroll
    for (int rr = 0; rr < 4; rr++) {
        int f = tid + rr * 256;
        int h = f >> 4;
        int c4 = (f & 15) * 4;
        float4 t = *(const float4*)&g_attn[abase + h * HDIM + c4];
        t.x = to_tf32(t.x); t.y = to_tf32(t.y); t.z = to_tf32(t.z); t.w = to_tf32(t.w);
        *(float4*)&sa[h * OPAD + c4] = t;
    }
    // load v tile (RNA-round)
    size_t vbase = ((size_t)b * SEQ + (size_t)st * 128) * EDIM + n * HDIM;
    #pragma unroll
    for (int rr = 0; rr < 8; rr++) {
        int f = tid + rr * 256;
        int row = f >> 4;
        int c4 = (f & 15) * 4;
        float4 t = *(const float4*)&gv[vbase + (size_t)row * EDIM + c4];
        t.x = to_tf32(t.x); t.y = to_tf32(t.y); t.z = to_tf32(t.z); t.w = to_tf32(t.w);
        *(float4*)&sv[row * OPAD + c4] = t;
    }
    __syncthreads();

    // 8 warps = 4(M) x 2(N); warp tile 32(s) x 32(hd); frags 2(M) x 4(N)
    int m0 = (wid & 3) * 32;
    int n0 = (wid >> 2) * 32;
    const uint32_t svb = smem_to_u32(sv);
    const uint32_t sab = smem_to_u32(sa);
    int q = lane >> 3, r = lane & 7;
    const uint32_t aBase = svb + (uint32_t)((m0 * OPAD + ((q & 1) * 8 + r) * OPAD + (q >> 1) * 4) * 4);
    const uint32_t bBase = sab + (uint32_t)((n0 * OPAD + ((q >> 1) * 8 + r) * OPAD + (q & 1) * 4) * 4);

    float acc[2][4][4];
    #pragma unroll
    for (int i = 0; i < 2; i++)
        #pragma unroll
        for (int j = 0; j < 4; j++)
            #pragma unroll
            for (int c = 0; c < 4; c++) acc[i][j][c] = 0.f;

    #pragma unroll
    for (int ks = 0; ks < 8; ks++) {
        uint32_t a[2][4];
        #pragma unroll
        for (int i = 0; i < 2; i++)
            ldsm_x4(a[i][0], a[i][1], a[i][2], a[i][3],
                    aBase + (uint32_t)(i * (16 * OPAD * 4) + ks * 32));
        uint32_t bfr[4][2];
        #pragma unroll
        for (int jp = 0; jp < 2; jp++)
            ldsm_x4(bfr[jp * 2][0], bfr[jp * 2][1], bfr[jp * 2 + 1][0], bfr[jp * 2 + 1][1],
                    bBase + (uint32_t)(jp * (16 * OPAD * 4) + ks * 32));
        #pragma unroll
        for (int i = 0; i < 2; i++)
            #pragma unroll
            for (int j = 0; j < 4; j++)
                mma_tf32(acc[i][j], a[i], bfr[j]);
    }

    size_t obase = ((size_t)b * SEQ + (size_t)st * 128) * EDIM + n * HDIM;
    #pragma unroll
    for (int i = 0; i < 2; i++) {
        int srow = m0 + 16 * i + g;
        #pragma unroll
        for (int j = 0; j < 4; j++) {
            int col = n0 + 8 * j + tig * 2;
            *(float2*)&g_o[obase + (size_t)srow * EDIM + col] =
                make_float2(acc[i][j][0], acc[i][j][1]);
            *(float2*)&g_o[obase + (size_t)(srow + 8) * EDIM + col] =
                make_float2(acc[i][j][2], acc[i][j][3]);
        }
    }
}

// ---------------- host launcher --------------------------------------------
extern "C" void kernel_launch(void* const* d_in, const int* in_sizes, int n_in,
                              void* d_out, int out_size)
{
    const float* query = (const float*)d_in[0];
    const float* gain  = (const float*)d_in[1];
    const float* wq    = (const float*)d_in[2];
    const float* wk    = (const float*)d_in[3];
    const float* wv    = (const float*)d_in[4];
    const float* wo    = (const float*)d_in[5];
    float* out = (float*)d_out;

    float *p_wn, *p_qkv, *p_o;
    cudaGetSymbolAddress((void**)&p_wn,  g_wn);
    cudaGetSymbolAddress((void**)&p_qkv, g_qkv);
    cudaGetSymbolAddress((void**)&p_o,   g_o);

    cudaFuncSetAttribute(gemm_tc_kernel,
                         cudaFuncAttributeMaxDynamicSharedMemorySize, GEMM_SMEM_BYTES);

    // 1) normalize weights (tf32-rounded)
    norm_weights_kernel<<<dim3(1024, 4), 256>>>(wq, wk, wv, wo, gain);

    // 2) fused Q/K/V projection
    dim3 qkvgrid(3 * EDIM / 128, TOK / 128);   // (24, 128)
    gemm_tc_kernel<<<qkvgrid, 256, GEMM_SMEM_BYTES>>>(query, p_wn, p_qkv, nullptr, 1.0f);

    // 3) partial scores on tensor cores (q/k head-norm fused, transposed smem)
    scores_part_tc_kernel<<<dim3(BH, NCHUNK), 256>>>();

    // 4) reduce + softmax
    softmax_kernel<<<512, 256>>>();

    // 5) apply attention weights to v (tensor cores, RNA-rounded)
    o_apply_tc_kernel<<<dim3(BH, 32), 256>>>();

    // 6) output projection + residual mix: (res + proj) * sqrt(0.5)
    dim3 ogrid(EDIM / 128, TOK / 128);         // (8, 128)
    gemm_tc_kernel<<<ogrid, 256, GEMM_SMEM_BYTES>>>(p_o, p_wn + 3u * (1024u * 1024u), out, query, 0.70710678118654752f);
}